// round 2
// baseline (speedup 1.0000x reference)
#include <cuda_runtime.h>
#include <math.h>

// Problem constants
#define B_   2
#define S_   2048
#define E_   1024
#define H_   16
#define D_   64
#define MTOT (B_ * S_)   // 4096

// Scratch buffers (allocation-free rule: __device__ globals)
__device__ float g_q[MTOT * E_];
__device__ float g_k[MTOT * E_];
__device__ float g_v[MTOT * E_];
__device__ float g_attn[MTOT * E_];

// ---------------------------------------------------------------------------
// GEMM (NT): Y[m][n] = sum_k X[m][k] * W[n][k] + bias[n]
// BM=BN=128, BK=16, 256 threads, 8x8 per thread.
// M, N, K assumed multiples of 128/128/16 (true for all uses here).
// ---------------------------------------------------------------------------
__global__ __launch_bounds__(256) void gemm_nt_bias(
    const float* __restrict__ X, const float* __restrict__ W,
    const float* __restrict__ bias, float* __restrict__ Y,
    int M, int N, int K)
{
    __shared__ float As[16][128];
    __shared__ float Bs[16][128];

    const int tid = threadIdx.x;
    const int tx = tid & 15;        // 0..15 -> n subtile
    const int ty = tid >> 4;        // 0..15 -> m subtile
    const int bm = blockIdx.y * 128;
    const int bn = blockIdx.x * 128;

    // loader mapping: 4 threads per row, each loads one float4 (4 k)
    const int lr = tid >> 2;        // 0..63
    const int lc = (tid & 3) << 2;  // 0,4,8,12

    const float* Xp  = X + (size_t)(bm + lr) * K + lc;
    const float* Xp2 = Xp + (size_t)64 * K;
    const float* Wp  = W + (size_t)(bn + lr) * K + lc;
    const float* Wp2 = Wp + (size_t)64 * K;

    float acc[8][8];
#pragma unroll
    for (int i = 0; i < 8; i++)
#pragma unroll
        for (int j = 0; j < 8; j++) acc[i][j] = 0.0f;

    for (int k0 = 0; k0 < K; k0 += 16) {
        float4 a0 = *(const float4*)(Xp  + k0);
        float4 a1 = *(const float4*)(Xp2 + k0);
        float4 b0 = *(const float4*)(Wp  + k0);
        float4 b1 = *(const float4*)(Wp2 + k0);

        As[lc + 0][lr]      = a0.x; As[lc + 1][lr]      = a0.y;
        As[lc + 2][lr]      = a0.z; As[lc + 3][lr]      = a0.w;
        As[lc + 0][lr + 64] = a1.x; As[lc + 1][lr + 64] = a1.y;
        As[lc + 2][lr + 64] = a1.z; As[lc + 3][lr + 64] = a1.w;

        Bs[lc + 0][lr]      = b0.x; Bs[lc + 1][lr]      = b0.y;
        Bs[lc + 2][lr]      = b0.z; Bs[lc + 3][lr]      = b0.w;
        Bs[lc + 0][lr + 64] = b1.x; Bs[lc + 1][lr + 64] = b1.y;
        Bs[lc + 2][lr + 64] = b1.z; Bs[lc + 3][lr + 64] = b1.w;

        __syncthreads();

#pragma unroll
        for (int kk = 0; kk < 16; kk++) {
            float a[8], b[8];
            *(float4*)&a[0] = *(const float4*)&As[kk][ty * 8];
            *(float4*)&a[4] = *(const float4*)&As[kk][ty * 8 + 4];
            *(float4*)&b[0] = *(const float4*)&Bs[kk][tx * 8];
            *(float4*)&b[4] = *(const float4*)&Bs[kk][tx * 8 + 4];
#pragma unroll
            for (int i = 0; i < 8; i++)
#pragma unroll
                for (int j = 0; j < 8; j++)
                    acc[i][j] += a[i] * b[j];
        }
        __syncthreads();
    }

    float bv[8];
    *(float4*)&bv[0] = *(const float4*)&bias[bn + tx * 8];
    *(float4*)&bv[4] = *(const float4*)&bias[bn + tx * 8 + 4];

#pragma unroll
    for (int i = 0; i < 8; i++) {
        float* yp = Y + (size_t)(bm + ty * 8 + i) * N + bn + tx * 8;
        float4 o0, o1;
        o0.x = acc[i][0] + bv[0]; o0.y = acc[i][1] + bv[1];
        o0.z = acc[i][2] + bv[2]; o0.w = acc[i][3] + bv[3];
        o1.x = acc[i][4] + bv[4]; o1.y = acc[i][5] + bv[5];
        o1.z = acc[i][6] + bv[6]; o1.w = acc[i][7] + bv[7];
        *(float4*)(yp)     = o0;
        *(float4*)(yp + 4) = o1;
    }
}

// ---------------------------------------------------------------------------
// Flash attention, fp32. One block per (q_tile=64, h, b). 256 threads.
// Tiles: Br=Bc=64, D=64. Online softmax. Q/K stored [d][row] (transposed),
// V stored [k][d], P stored [q][k] with pad 68 (16B-aligned rows).
// q/k/v layout in gmem: (B*S, E) row-major, head h at column h*D.
// ---------------------------------------------------------------------------
#define PS_LD 68
#define FA_SMEM ((3 * 64 * 64 + 64 * PS_LD) * 4)   // 66560 bytes

__global__ __launch_bounds__(256) void flash_attn_kernel(
    const float* __restrict__ Q, const float* __restrict__ Kg,
    const float* __restrict__ Vg, float* __restrict__ O)
{
    extern __shared__ float sm[];
    float* Qs = sm;               // [64][64] : Qs[d*64 + q]
    float* Ks = sm + 4096;        // [64][64] : Ks[d*64 + k]
    float* Vs = sm + 8192;        // [64][64] : Vs[k*64 + d]
    float* Ps = sm + 12288;       // [64][68] : Ps[q*68 + k]

    const int tid = threadIdx.x;
    const int tx = tid & 15;      // key / d subtile
    const int ty = tid >> 4;      // query subtile
    const int q0 = blockIdx.x * 64;
    const int h  = blockIdx.y;
    const int b  = blockIdx.z;
    const float scale = 0.125f;   // 1/sqrt(64)

    const size_t base = ((size_t)b * S_) * E_ + (size_t)h * D_;
    const float* Qb = Q  + base;
    const float* Kb = Kg + base;
    const float* Vb = Vg + base;

    // loader mapping: lr = row (0..63), lc = d-chunk start {0,16,32,48}
    const int lr = tid >> 2;
    const int lc = (tid & 3) << 4;

    // Load Q tile transposed (once)
#pragma unroll
    for (int ii = 0; ii < 16; ii += 4) {
        float4 v = *(const float4*)&Qb[(size_t)(q0 + lr) * E_ + lc + ii];
        Qs[(lc + ii + 0) * 64 + lr] = v.x;
        Qs[(lc + ii + 1) * 64 + lr] = v.y;
        Qs[(lc + ii + 2) * 64 + lr] = v.z;
        Qs[(lc + ii + 3) * 64 + lr] = v.w;
    }

    float m_i[4], l_i[4], o[4][4];
#pragma unroll
    for (int i = 0; i < 4; i++) {
        m_i[i] = -INFINITY; l_i[i] = 0.0f;
#pragma unroll
        for (int j = 0; j < 4; j++) o[i][j] = 0.0f;
    }

    for (int kt = 0; kt < S_; kt += 64) {
        __syncthreads();  // protect Ks/Vs/Ps from previous iteration readers

        // Load K (transposed) and V (direct)
#pragma unroll
        for (int ii = 0; ii < 16; ii += 4) {
            float4 kv = *(const float4*)&Kb[(size_t)(kt + lr) * E_ + lc + ii];
            Ks[(lc + ii + 0) * 64 + lr] = kv.x;
            Ks[(lc + ii + 1) * 64 + lr] = kv.y;
            Ks[(lc + ii + 2) * 64 + lr] = kv.z;
            Ks[(lc + ii + 3) * 64 + lr] = kv.w;
            *(float4*)&Vs[lr * 64 + lc + ii] =
                *(const float4*)&Vb[(size_t)(kt + lr) * E_ + lc + ii];
        }
        __syncthreads();

        // GEMM1: s = Q K^T (4x4 per thread)
        float s[4][4];
#pragma unroll
        for (int i = 0; i < 4; i++)
#pragma unroll
            for (int j = 0; j < 4; j++) s[i][j] = 0.0f;

#pragma unroll 8
        for (int d = 0; d < 64; d++) {
            float qv[4], kv[4];
            *(float4*)qv = *(const float4*)&Qs[d * 64 + ty * 4];
            *(float4*)kv = *(const float4*)&Ks[d * 64 + tx * 4];
#pragma unroll
            for (int i = 0; i < 4; i++)
#pragma unroll
                for (int j = 0; j < 4; j++)
                    s[i][j] += qv[i] * kv[j];
        }

        // Online softmax update (row groups: 16 lanes with same ty)
#pragma unroll
        for (int i = 0; i < 4; i++) {
            float mx = s[i][0] * scale;
            mx = fmaxf(mx, s[i][1] * scale);
            mx = fmaxf(mx, s[i][2] * scale);
            mx = fmaxf(mx, s[i][3] * scale);
#pragma unroll
            for (int off = 1; off < 16; off <<= 1)
                mx = fmaxf(mx, __shfl_xor_sync(0xffffffffu, mx, off));
            float mnew = fmaxf(m_i[i], mx);
            float alpha = __expf(m_i[i] - mnew);
            float rs = 0.0f;
#pragma unroll
            for (int j = 0; j < 4; j++) {
                float p = __expf(s[i][j] * scale - mnew);
                s[i][j] = p;
                rs += p;
            }
#pragma unroll
            for (int off = 1; off < 16; off <<= 1)
                rs += __shfl_xor_sync(0xffffffffu, rs, off);
            l_i[i] = l_i[i] * alpha + rs;
            m_i[i] = mnew;
#pragma unroll
            for (int j = 0; j < 4; j++) o[i][j] *= alpha;
        }

        // Write P to shared
#pragma unroll
        for (int i = 0; i < 4; i++)
#pragma unroll
            for (int j = 0; j < 4; j++)
                Ps[(ty * 4 + i) * PS_LD + tx * 4 + j] = s[i][j];
        __syncthreads();

        // GEMM2: o += P @ V   (k unrolled by 4, vectorized P and V reads)
#pragma unroll 4
        for (int k = 0; k < 64; k += 4) {
            float vv[4][4];
#pragma unroll
            for (int kk = 0; kk < 4; kk++)
                *(float4*)vv[kk] = *(const float4*)&Vs[(k + kk) * 64 + tx * 4];
#pragma unroll
            for (int i = 0; i < 4; i++) {
                float pv[4];
                *(float4*)pv = *(const float4*)&Ps[(ty * 4 + i) * PS_LD + k];
#pragma unroll
                for (int kk = 0; kk < 4; kk++)
#pragma unroll
                    for (int j = 0; j < 4; j++)
                        o[i][j] += pv[kk] * vv[kk][j];
            }
        }
    }

    // Epilogue: normalize and write O (layout (B*S, E), head column block)
    float* Ob = O + base;
#pragma unroll
    for (int i = 0; i < 4; i++) {
        float inv = 1.0f / l_i[i];
        float4 r;
        r.x = o[i][0] * inv; r.y = o[i][1] * inv;
        r.z = o[i][2] * inv; r.w = o[i][3] * inv;
        *(float4*)&Ob[(size_t)(q0 + ty * 4 + i) * E_ + tx * 4] = r;
    }
}

// ---------------------------------------------------------------------------
// Launch
// ---------------------------------------------------------------------------
extern "C" void kernel_launch(void* const* d_in, const int* in_sizes, int n_in,
                              void* d_out, int out_size)
{
    (void)in_sizes; (void)n_in; (void)out_size;

    const float* q     = (const float*)d_in[0];
    const float* k     = (const float*)d_in[1];
    const float* v     = (const float*)d_in[2];
    const float* w_in  = (const float*)d_in[3];
    const float* b_in  = (const float*)d_in[4];
    const float* w_out = (const float*)d_in[5];
    const float* b_out = (const float*)d_in[6];
    float* out = (float*)d_out;

    float *gq, *gk, *gv, *ga;
    cudaGetSymbolAddress((void**)&gq, g_q);
    cudaGetSymbolAddress((void**)&gk, g_k);
    cudaGetSymbolAddress((void**)&gv, g_v);
    cudaGetSymbolAddress((void**)&ga, g_attn);

    cudaFuncSetAttribute(flash_attn_kernel,
                         cudaFuncAttributeMaxDynamicSharedMemorySize, FA_SMEM);

    dim3 gg(E_ / 128, MTOT / 128);   // (8, 32)

    gemm_nt_bias<<<gg, 256>>>(q, w_in,                         b_in,          gq, MTOT, E_, E_);
    gemm_nt_bias<<<gg, 256>>>(k, w_in + (size_t)E_ * E_,       b_in + E_,     gk, MTOT, E_, E_);
    gemm_nt_bias<<<gg, 256>>>(v, w_in + (size_t)2 * E_ * E_,   b_in + 2 * E_, gv, MTOT, E_, E_);

    dim3 fg(S_ / 64, H_, B_);        // (32, 16, 2)
    flash_attn_kernel<<<fg, 256, FA_SMEM>>>(gq, gk, gv, ga);

    gemm_nt_bias<<<gg, 256>>>(ga, w_out, b_out, out, MTOT, E_, E_);
}

// round 7
// speedup vs baseline: 1.3881x; 1.3881x over previous
#include <cuda_runtime.h>
#include <cuda_bf16.h>
#include <cstdint>
#include <math.h>

// Problem constants
#define B_   2
#define S_   2048
#define E_   1024
#define H_   16
#define D_   64
#define MTOT (B_ * S_)   // 4096

// Scratch buffers (allocation-free rule: __device__ globals)
__device__ float g_q[MTOT * E_];
__device__ float g_k[MTOT * E_];
__device__ float g_v[MTOT * E_];
__device__ float g_attn[MTOT * E_];

__device__ __forceinline__ uint32_t smem_u32(const void* p) {
    uint32_t a;
    asm("{ .reg .u64 t; cvta.to.shared.u64 t, %1; cvt.u32.u64 %0, t; }"
        : "=r"(a) : "l"(p));
    return a;
}

#define SWZ128(off) ((off) ^ (((off) >> 3) & 0x70))

__device__ __forceinline__ void ldsm_x4(uint32_t addr, uint32_t* r) {
    asm volatile(
        "ldmatrix.sync.aligned.m8n8.x4.shared.b16 {%0,%1,%2,%3}, [%4];"
        : "=r"(r[0]), "=r"(r[1]), "=r"(r[2]), "=r"(r[3]) : "r"(addr));
}

__device__ __forceinline__ void mma16816(float* d, const uint32_t* a, const uint32_t* b) {
    asm volatile(
        "mma.sync.aligned.m16n8k16.row.col.f32.bf16.bf16.f32 "
        "{%0,%1,%2,%3}, {%4,%5,%6,%7}, {%8,%9}, {%0,%1,%2,%3};"
        : "+f"(d[0]), "+f"(d[1]), "+f"(d[2]), "+f"(d[3])
        : "r"(a[0]), "r"(a[1]), "r"(a[2]), "r"(a[3]), "r"(b[0]), "r"(b[1]));
}

// split one float4 into hi/lo bf16 pairs (packed as uint2 = 4 bf16)
__device__ __forceinline__ void split4(float4 v, uint2& h, uint2& l)
{
    __nv_bfloat162 h01 = __floats2bfloat162_rn(v.x, v.y);
    __nv_bfloat162 h23 = __floats2bfloat162_rn(v.z, v.w);
    float2 f01 = __bfloat1622float2(h01);
    float2 f23 = __bfloat1622float2(h23);
    __nv_bfloat162 l01 = __floats2bfloat162_rn(v.x - f01.x, v.y - f01.y);
    __nv_bfloat162 l23 = __floats2bfloat162_rn(v.z - f23.x, v.w - f23.y);
    h.x = *reinterpret_cast<uint32_t*>(&h01);
    h.y = *reinterpret_cast<uint32_t*>(&h23);
    l.x = *reinterpret_cast<uint32_t*>(&l01);
    l.y = *reinterpret_cast<uint32_t*>(&l23);
}

// ===========================================================================
// Tensor-core GEMM (NT) via mma.sync: Y[m][n] = sum_k X[m][k]*W[n][k] + bias[n]
// bf16 2-way split, 3 products, fp32 register accum.
// Tile 128x128, BK=64. 8 warps: warp_m = wid&1 (64 rows), warp_n = wid>>1 (32 cols).
// SMEM: Ahi/Alo/Bhi/Blo, each [128 rows][64 bf16] = 128B/row, SW128 swizzle.
// ===========================================================================
#define TILE_B    16384                    // 128 rows x 128 bytes
#define GEMM_SMEM (4 * TILE_B)             // 65536

__global__ __launch_bounds__(256, 2) void gemm_tc(
    const float* __restrict__ X, const float* __restrict__ W,
    const float* __restrict__ bias, float* __restrict__ Y,
    int K, int N)
{
    extern __shared__ char smem[];
    char* Ahi = smem;
    char* Alo = smem + TILE_B;
    char* Bhi = smem + 2 * TILE_B;
    char* Blo = smem + 3 * TILE_B;
    const uint32_t sAhi = smem_u32(Ahi);
    const uint32_t sAlo = sAhi + TILE_B;
    const uint32_t sBhi = sAhi + 2 * TILE_B;
    const uint32_t sBlo = sAhi + 3 * TILE_B;

    const int t    = threadIdx.x;
    const int wid  = t >> 5;
    const int lane = t & 31;
    const int bm   = blockIdx.y * 128;
    const int bn   = blockIdx.x * 128;
    const int wm   = (wid & 1) * 64;      // warp m offset in tile
    const int wn   = (wid >> 1) * 32;     // warp n offset in tile

    float acc[4][4][4];
#pragma unroll
    for (int i = 0; i < 4; i++)
#pragma unroll
        for (int j = 0; j < 4; j++)
#pragma unroll
            for (int r = 0; r < 4; r++) acc[i][j][r] = 0.0f;

    // ldmatrix address precompute (byte offsets within a tile, swizzled later)
    const int a_row = (lane & 15);            // + mtile base
    const int a_kb  = ((lane >> 4) & 1) * 16; // + kstep*32
    const int b_row = ((lane >> 4) & 1) * 8 + (lane & 7); // + ntile-pair base
    const int b_kb  = ((lane >> 3) & 1) * 16;

    for (int k0 = 0; k0 < K; k0 += 64) {
        __syncthreads();
        // ---- load chunk: fp32 gmem -> split bf16 -> swizzled smem ----
#pragma unroll
        for (int i = 0; i < 8; ++i) {
            const int f    = t + 256 * i;      // 0..2047
            const int row  = f >> 4;           // 0..127
            const int quad = f & 15;           // 16 float4 per row
            const uint32_t off = SWZ128((uint32_t)(row * 128 + quad * 8));
            float4 va = *(const float4*)&X[(size_t)(bm + row) * K + k0 + quad * 4];
            float4 vb = *(const float4*)&W[(size_t)(bn + row) * K + k0 + quad * 4];
            uint2 h, l;
            split4(va, h, l);
            *(uint2*)(Ahi + off) = h;
            *(uint2*)(Alo + off) = l;
            split4(vb, h, l);
            *(uint2*)(Bhi + off) = h;
            *(uint2*)(Blo + off) = l;
        }
        __syncthreads();

        // ---- compute: 4 k-steps of 16 ----
#pragma unroll
        for (int ks = 0; ks < 4; ++ks) {
            const int kb = ks * 32;
            // B fragments: 4 n-tiles (two x4 loads each for hi/lo)
            uint32_t bh[4][2], bl[4][2];
#pragma unroll
            for (int np = 0; np < 2; ++np) {
                const uint32_t boff =
                    SWZ128((uint32_t)((wn + np * 16 + b_row) * 128 + kb + b_kb));
                uint32_t r4[4];
                ldsm_x4(sBhi + boff, r4);
                bh[2 * np][0] = r4[0]; bh[2 * np][1] = r4[1];
                bh[2 * np + 1][0] = r4[2]; bh[2 * np + 1][1] = r4[3];
                ldsm_x4(sBlo + boff, r4);
                bl[2 * np][0] = r4[0]; bl[2 * np][1] = r4[1];
                bl[2 * np + 1][0] = r4[2]; bl[2 * np + 1][1] = r4[3];
            }
#pragma unroll
            for (int mt = 0; mt < 4; ++mt) {
                const uint32_t aoff =
                    SWZ128((uint32_t)((wm + mt * 16 + a_row) * 128 + kb + a_kb));
                uint32_t ah[4], al[4];
                ldsm_x4(sAhi + aoff, ah);
                ldsm_x4(sAlo + aoff, al);
#pragma unroll
                for (int nt = 0; nt < 4; ++nt) {
                    mma16816(acc[mt][nt], ah, bh[nt]);
                    mma16816(acc[mt][nt], ah, bl[nt]);
                    mma16816(acc[mt][nt], al, bh[nt]);
                }
            }
        }
    }

    // ---- epilogue: c-frag layout -> gmem, add bias ----
    const int cr = lane >> 2;          // 0..7
    const int cc = (lane & 3) * 2;     // 0,2,4,6
#pragma unroll
    for (int mt = 0; mt < 4; ++mt) {
        const int row0 = bm + wm + mt * 16 + cr;
#pragma unroll
        for (int nt = 0; nt < 4; ++nt) {
            const int col = bn + wn + nt * 8 + cc;
            const float2 bv = *(const float2*)&bias[col];
            float2 v0, v1;
            v0.x = acc[mt][nt][0] + bv.x; v0.y = acc[mt][nt][1] + bv.y;
            v1.x = acc[mt][nt][2] + bv.x; v1.y = acc[mt][nt][3] + bv.y;
            *(float2*)&Y[(size_t)row0 * N + col]       = v0;
            *(float2*)&Y[(size_t)(row0 + 8) * N + col] = v1;
        }
    }
}

// ---------------------------------------------------------------------------
// Flash attention, fp32 (unchanged from passing baseline).
// ---------------------------------------------------------------------------
#define PS_LD 68
#define FA_SMEM ((3 * 64 * 64 + 64 * PS_LD) * 4)   // 66560 bytes

__global__ __launch_bounds__(256) void flash_attn_kernel(
    const float* __restrict__ Q, const float* __restrict__ Kg,
    const float* __restrict__ Vg, float* __restrict__ O)
{
    extern __shared__ float sm[];
    float* Qs = sm;               // [64][64] : Qs[d*64 + q]
    float* Ks = sm + 4096;        // [64][64] : Ks[d*64 + k]
    float* Vs = sm + 8192;        // [64][64] : Vs[k*64 + d]
    float* Ps = sm + 12288;       // [64][68] : Ps[q*68 + k]

    const int tid = threadIdx.x;
    const int tx = tid & 15;
    const int ty = tid >> 4;
    const int q0 = blockIdx.x * 64;
    const int h  = blockIdx.y;
    const int b  = blockIdx.z;
    const float scale = 0.125f;

    const size_t base = ((size_t)b * S_) * E_ + (size_t)h * D_;
    const float* Qb = Q  + base;
    const float* Kb = Kg + base;
    const float* Vb = Vg + base;

    const int lr = tid >> 2;
    const int lc = (tid & 3) << 4;

#pragma unroll
    for (int ii = 0; ii < 16; ii += 4) {
        float4 v = *(const float4*)&Qb[(size_t)(q0 + lr) * E_ + lc + ii];
        Qs[(lc + ii + 0) * 64 + lr] = v.x;
        Qs[(lc + ii + 1) * 64 + lr] = v.y;
        Qs[(lc + ii + 2) * 64 + lr] = v.z;
        Qs[(lc + ii + 3) * 64 + lr] = v.w;
    }

    float m_i[4], l_i[4], o[4][4];
#pragma unroll
    for (int i = 0; i < 4; i++) {
        m_i[i] = -INFINITY; l_i[i] = 0.0f;
#pragma unroll
        for (int j = 0; j < 4; j++) o[i][j] = 0.0f;
    }

    for (int kt = 0; kt < S_; kt += 64) {
        __syncthreads();

#pragma unroll
        for (int ii = 0; ii < 16; ii += 4) {
            float4 kv = *(const float4*)&Kb[(size_t)(kt + lr) * E_ + lc + ii];
            Ks[(lc + ii + 0) * 64 + lr] = kv.x;
            Ks[(lc + ii + 1) * 64 + lr] = kv.y;
            Ks[(lc + ii + 2) * 64 + lr] = kv.z;
            Ks[(lc + ii + 3) * 64 + lr] = kv.w;
            *(float4*)&Vs[lr * 64 + lc + ii] =
                *(const float4*)&Vb[(size_t)(kt + lr) * E_ + lc + ii];
        }
        __syncthreads();

        float s[4][4];
#pragma unroll
        for (int i = 0; i < 4; i++)
#pragma unroll
            for (int j = 0; j < 4; j++) s[i][j] = 0.0f;

#pragma unroll 8
        for (int d = 0; d < 64; d++) {
            float qv[4], kv[4];
            *(float4*)qv = *(const float4*)&Qs[d * 64 + ty * 4];
            *(float4*)kv = *(const float4*)&Ks[d * 64 + tx * 4];
#pragma unroll
            for (int i = 0; i < 4; i++)
#pragma unroll
                for (int j = 0; j < 4; j++)
                    s[i][j] += qv[i] * kv[j];
        }

#pragma unroll
        for (int i = 0; i < 4; i++) {
            float mx = s[i][0] * scale;
            mx = fmaxf(mx, s[i][1] * scale);
            mx = fmaxf(mx, s[i][2] * scale);
            mx = fmaxf(mx, s[i][3] * scale);
#pragma unroll
            for (int off = 1; off < 16; off <<= 1)
                mx = fmaxf(mx, __shfl_xor_sync(0xffffffffu, mx, off));
            float mnew = fmaxf(m_i[i], mx);
            float alpha = __expf(m_i[i] - mnew);
            float rs = 0.0f;
#pragma unroll
            for (int j = 0; j < 4; j++) {
                float p = __expf(s[i][j] * scale - mnew);
                s[i][j] = p;
                rs += p;
            }
#pragma unroll
            for (int off = 1; off < 16; off <<= 1)
                rs += __shfl_xor_sync(0xffffffffu, rs, off);
            l_i[i] = l_i[i] * alpha + rs;
            m_i[i] = mnew;
#pragma unroll
            for (int j = 0; j < 4; j++) o[i][j] *= alpha;
        }

#pragma unroll
        for (int i = 0; i < 4; i++)
#pragma unroll
            for (int j = 0; j < 4; j++)
                Ps[(ty * 4 + i) * PS_LD + tx * 4 + j] = s[i][j];
        __syncthreads();

#pragma unroll 4
        for (int k = 0; k < 64; k += 4) {
            float vv[4][4];
#pragma unroll
            for (int kk = 0; kk < 4; kk++)
                *(float4*)vv[kk] = *(const float4*)&Vs[(k + kk) * 64 + tx * 4];
#pragma unroll
            for (int i = 0; i < 4; i++) {
                float pv[4];
                *(float4*)pv = *(const float4*)&Ps[(ty * 4 + i) * PS_LD + k];
#pragma unroll
                for (int kk = 0; kk < 4; kk++)
#pragma unroll
                    for (int j = 0; j < 4; j++)
                        o[i][j] += pv[kk] * vv[kk][j];
            }
        }
    }

    float* Ob = O + base;
#pragma unroll
    for (int i = 0; i < 4; i++) {
        float inv = 1.0f / l_i[i];
        float4 r;
        r.x = o[i][0] * inv; r.y = o[i][1] * inv;
        r.z = o[i][2] * inv; r.w = o[i][3] * inv;
        *(float4*)&Ob[(size_t)(q0 + ty * 4 + i) * E_ + tx * 4] = r;
    }
}

// ---------------------------------------------------------------------------
// Launch
// ---------------------------------------------------------------------------
extern "C" void kernel_launch(void* const* d_in, const int* in_sizes, int n_in,
                              void* d_out, int out_size)
{
    (void)in_sizes; (void)n_in; (void)out_size;

    const float* q     = (const float*)d_in[0];
    const float* k     = (const float*)d_in[1];
    const float* v     = (const float*)d_in[2];
    const float* w_in  = (const float*)d_in[3];
    const float* b_in  = (const float*)d_in[4];
    const float* w_out = (const float*)d_in[5];
    const float* b_out = (const float*)d_in[6];
    float* out = (float*)d_out;

    float *gq, *gk, *gv, *ga;
    cudaGetSymbolAddress((void**)&gq, g_q);
    cudaGetSymbolAddress((void**)&gk, g_k);
    cudaGetSymbolAddress((void**)&gv, g_v);
    cudaGetSymbolAddress((void**)&ga, g_attn);

    cudaFuncSetAttribute(gemm_tc,
                         cudaFuncAttributeMaxDynamicSharedMemorySize, GEMM_SMEM);
    cudaFuncSetAttribute(flash_attn_kernel,
                         cudaFuncAttributeMaxDynamicSharedMemorySize, FA_SMEM);

    dim3 gg(E_ / 128, MTOT / 128);   // (8, 32)

    gemm_tc<<<gg, 256, GEMM_SMEM>>>(q, w_in,                       b_in,          gq, E_, E_);
    gemm_tc<<<gg, 256, GEMM_SMEM>>>(k, w_in + (size_t)E_ * E_,     b_in + E_,     gk, E_, E_);
    gemm_tc<<<gg, 256, GEMM_SMEM>>>(v, w_in + (size_t)2 * E_ * E_, b_in + 2 * E_, gv, E_, E_);

    dim3 fg(S_ / 64, H_, B_);        // (32, 16, 2)
    flash_attn_kernel<<<fg, 256, FA_SMEM>>>(gq, gk, gv, ga);

    gemm_tc<<<gg, 256, GEMM_SMEM>>>(ga, w_out, b_out, out, E_, E_);
}

// round 8
// speedup vs baseline: 2.7347x; 1.9701x over previous
#include <cuda_runtime.h>
#include <cuda_bf16.h>
#include <cstdint>
#include <math.h>

// Problem constants
#define B_   2
#define S_   2048
#define E_   1024
#define H_   16
#define D_   64
#define MTOT (B_ * S_)   // 4096

// Scratch buffers (allocation-free rule: __device__ globals)
__device__ float g_q[MTOT * E_];
__device__ float g_k[MTOT * E_];
__device__ float g_v[MTOT * E_];
__device__ float g_attn[MTOT * E_];

__device__ __forceinline__ uint32_t smem_u32(const void* p) {
    uint32_t a;
    asm("{ .reg .u64 t; cvta.to.shared.u64 t, %1; cvt.u32.u64 %0, t; }"
        : "=r"(a) : "l"(p));
    return a;
}

#define SWZ128(off) ((off) ^ (((off) >> 3) & 0x70))

__device__ __forceinline__ void ldsm_x4(uint32_t addr, uint32_t* r) {
    asm volatile(
        "ldmatrix.sync.aligned.m8n8.x4.shared.b16 {%0,%1,%2,%3}, [%4];"
        : "=r"(r[0]), "=r"(r[1]), "=r"(r[2]), "=r"(r[3]) : "r"(addr));
}

__device__ __forceinline__ void ldsm_x4_t(uint32_t addr, uint32_t* r) {
    asm volatile(
        "ldmatrix.sync.aligned.m8n8.x4.trans.shared.b16 {%0,%1,%2,%3}, [%4];"
        : "=r"(r[0]), "=r"(r[1]), "=r"(r[2]), "=r"(r[3]) : "r"(addr));
}

__device__ __forceinline__ void mma16816(float* d, const uint32_t* a, const uint32_t* b) {
    asm volatile(
        "mma.sync.aligned.m16n8k16.row.col.f32.bf16.bf16.f32 "
        "{%0,%1,%2,%3}, {%4,%5,%6,%7}, {%8,%9}, {%0,%1,%2,%3};"
        : "+f"(d[0]), "+f"(d[1]), "+f"(d[2]), "+f"(d[3])
        : "r"(a[0]), "r"(a[1]), "r"(a[2]), "r"(a[3]), "r"(b[0]), "r"(b[1]));
}

// split one float4 into hi/lo bf16 pairs (packed as uint2 = 4 bf16)
__device__ __forceinline__ void split4(float4 v, uint2& h, uint2& l)
{
    __nv_bfloat162 h01 = __floats2bfloat162_rn(v.x, v.y);
    __nv_bfloat162 h23 = __floats2bfloat162_rn(v.z, v.w);
    float2 f01 = __bfloat1622float2(h01);
    float2 f23 = __bfloat1622float2(h23);
    __nv_bfloat162 l01 = __floats2bfloat162_rn(v.x - f01.x, v.y - f01.y);
    __nv_bfloat162 l23 = __floats2bfloat162_rn(v.z - f23.x, v.w - f23.y);
    h.x = *reinterpret_cast<uint32_t*>(&h01);
    h.y = *reinterpret_cast<uint32_t*>(&h23);
    l.x = *reinterpret_cast<uint32_t*>(&l01);
    l.y = *reinterpret_cast<uint32_t*>(&l23);
}

// split two floats into packed bf16x2 hi + lo
__device__ __forceinline__ void split2(float a, float b, uint32_t& hi, uint32_t& lo)
{
    __nv_bfloat162 h = __floats2bfloat162_rn(a, b);
    float2 f = __bfloat1622float2(h);
    __nv_bfloat162 l = __floats2bfloat162_rn(a - f.x, b - f.y);
    hi = *reinterpret_cast<uint32_t*>(&h);
    lo = *reinterpret_cast<uint32_t*>(&l);
}

// ===========================================================================
// Tensor-core GEMM (NT) via mma.sync (unchanged from R7 WIN)
// ===========================================================================
#define TILE_B    16384
#define GEMM_SMEM (4 * TILE_B)

__global__ __launch_bounds__(256, 2) void gemm_tc(
    const float* __restrict__ X, const float* __restrict__ W,
    const float* __restrict__ bias, float* __restrict__ Y,
    int K, int N)
{
    extern __shared__ char smem[];
    char* Ahi = smem;
    char* Alo = smem + TILE_B;
    char* Bhi = smem + 2 * TILE_B;
    char* Blo = smem + 3 * TILE_B;
    const uint32_t sAhi = smem_u32(Ahi);
    const uint32_t sAlo = sAhi + TILE_B;
    const uint32_t sBhi = sAhi + 2 * TILE_B;
    const uint32_t sBlo = sAhi + 3 * TILE_B;

    const int t    = threadIdx.x;
    const int wid  = t >> 5;
    const int lane = t & 31;
    const int bm   = blockIdx.y * 128;
    const int bn   = blockIdx.x * 128;
    const int wm   = (wid & 1) * 64;
    const int wn   = (wid >> 1) * 32;

    float acc[4][4][4];
#pragma unroll
    for (int i = 0; i < 4; i++)
#pragma unroll
        for (int j = 0; j < 4; j++)
#pragma unroll
            for (int r = 0; r < 4; r++) acc[i][j][r] = 0.0f;

    const int a_row = (lane & 15);
    const int a_kb  = ((lane >> 4) & 1) * 16;
    const int b_row = ((lane >> 4) & 1) * 8 + (lane & 7);
    const int b_kb  = ((lane >> 3) & 1) * 16;

    for (int k0 = 0; k0 < K; k0 += 64) {
        __syncthreads();
#pragma unroll
        for (int i = 0; i < 8; ++i) {
            const int f    = t + 256 * i;
            const int row  = f >> 4;
            const int quad = f & 15;
            const uint32_t off = SWZ128((uint32_t)(row * 128 + quad * 8));
            float4 va = *(const float4*)&X[(size_t)(bm + row) * K + k0 + quad * 4];
            float4 vb = *(const float4*)&W[(size_t)(bn + row) * K + k0 + quad * 4];
            uint2 h, l;
            split4(va, h, l);
            *(uint2*)(Ahi + off) = h;
            *(uint2*)(Alo + off) = l;
            split4(vb, h, l);
            *(uint2*)(Bhi + off) = h;
            *(uint2*)(Blo + off) = l;
        }
        __syncthreads();

#pragma unroll
        for (int ks = 0; ks < 4; ++ks) {
            const int kb = ks * 32;
            uint32_t bh[4][2], bl[4][2];
#pragma unroll
            for (int np = 0; np < 2; ++np) {
                const uint32_t boff =
                    SWZ128((uint32_t)((wn + np * 16 + b_row) * 128 + kb + b_kb));
                uint32_t r4[4];
                ldsm_x4(sBhi + boff, r4);
                bh[2 * np][0] = r4[0]; bh[2 * np][1] = r4[1];
                bh[2 * np + 1][0] = r4[2]; bh[2 * np + 1][1] = r4[3];
                ldsm_x4(sBlo + boff, r4);
                bl[2 * np][0] = r4[0]; bl[2 * np][1] = r4[1];
                bl[2 * np + 1][0] = r4[2]; bl[2 * np + 1][1] = r4[3];
            }
#pragma unroll
            for (int mt = 0; mt < 4; ++mt) {
                const uint32_t aoff =
                    SWZ128((uint32_t)((wm + mt * 16 + a_row) * 128 + kb + a_kb));
                uint32_t ah[4], al[4];
                ldsm_x4(sAhi + aoff, ah);
                ldsm_x4(sAlo + aoff, al);
#pragma unroll
                for (int nt = 0; nt < 4; ++nt) {
                    mma16816(acc[mt][nt], ah, bh[nt]);
                    mma16816(acc[mt][nt], ah, bl[nt]);
                    mma16816(acc[mt][nt], al, bh[nt]);
                }
            }
        }
    }

    const int cr = lane >> 2;
    const int cc = (lane & 3) * 2;
#pragma unroll
    for (int mt = 0; mt < 4; ++mt) {
        const int row0 = bm + wm + mt * 16 + cr;
#pragma unroll
        for (int nt = 0; nt < 4; ++nt) {
            const int col = bn + wn + nt * 8 + cc;
            const float2 bv = *(const float2*)&bias[col];
            float2 v0, v1;
            v0.x = acc[mt][nt][0] + bv.x; v0.y = acc[mt][nt][1] + bv.y;
            v1.x = acc[mt][nt][2] + bv.x; v1.y = acc[mt][nt][3] + bv.y;
            *(float2*)&Y[(size_t)row0 * N + col]       = v0;
            *(float2*)&Y[(size_t)(row0 + 8) * N + col] = v1;
        }
    }
}

// ===========================================================================
// Tensor-core flash attention, split-bf16 (3-product) QK^T and PV.
// CTA: 128 q-rows, 8 warps x 16 rows. Bc=64 keys/iter. Warp-local softmax.
// SMEM: Qhi/Qlo [128][64bf16], Khi/Klo [64][64], Vhi/Vlo [64][64] = 64 KB.
// ===========================================================================
#define FA_SMEM 65536

__global__ __launch_bounds__(256) void flash_tc(
    const float* __restrict__ Q, const float* __restrict__ Kg,
    const float* __restrict__ Vg, float* __restrict__ O)
{
    extern __shared__ char smem[];
    char* Qhi = smem;                 // 16384
    char* Qlo = smem + 16384;         // 16384
    char* Khi = smem + 32768;         // 8192
    char* Klo = smem + 40960;         // 8192
    char* Vhi = smem + 49152;         // 8192
    char* Vlo = smem + 57344;         // 8192
    const uint32_t sQhi = smem_u32(Qhi);
    const uint32_t sQlo = sQhi + 16384;
    const uint32_t sKhi = sQhi + 32768;
    const uint32_t sKlo = sQhi + 40960;
    const uint32_t sVhi = sQhi + 49152;
    const uint32_t sVlo = sQhi + 57344;

    const int t    = threadIdx.x;
    const int wid  = t >> 5;
    const int lane = t & 31;
    const int q0   = blockIdx.x * 128;
    const int h    = blockIdx.y;
    const int b    = blockIdx.z;
    const float scale = 0.125f;

    const size_t base = ((size_t)b * S_) * E_ + (size_t)h * D_;
    const float* Qb = Q  + base;
    const float* Kb = Kg + base;
    const float* Vb = Vg + base;

    // ---- load Q tile (once): 128 rows x 16 float4 ----
#pragma unroll
    for (int i = 0; i < 8; ++i) {
        const int f    = t + 256 * i;
        const int row  = f >> 4;
        const int quad = f & 15;
        const uint32_t off = SWZ128((uint32_t)(row * 128 + quad * 8));
        float4 v = *(const float4*)&Qb[(size_t)(q0 + row) * E_ + quad * 4];
        uint2 hh, ll;
        split4(v, hh, ll);
        *(uint2*)(Qhi + off) = hh;
        *(uint2*)(Qlo + off) = ll;
    }
    __syncthreads();

    // ---- hoist Q fragments (A-frag, 4 k-steps, hi+lo) ----
    const int a_row = (lane & 15);
    const int a_kb  = ((lane >> 4) & 1) * 16;
    uint32_t qh[4][4], ql[4][4];
#pragma unroll
    for (int ks = 0; ks < 4; ++ks) {
        const uint32_t aoff =
            SWZ128((uint32_t)((wid * 16 + a_row) * 128 + ks * 32 + a_kb));
        ldsm_x4(sQhi + aoff, qh[ks]);
        ldsm_x4(sQlo + aoff, ql[ks]);
    }

    // B-frag lane mapping for K (non-trans) and V (trans)
    const int b_row = ((lane >> 4) & 1) * 8 + (lane & 7);
    const int b_kb  = ((lane >> 3) & 1) * 16;
    const int v_row = ((lane >> 3) & 1) * 8 + (lane & 7);
    const int v_db  = ((lane >> 4) & 1) * 16;

    float m0 = -INFINITY, m1 = -INFINITY, l0 = 0.0f, l1 = 0.0f;
    float oa[8][4];
#pragma unroll
    for (int nt = 0; nt < 8; ++nt)
#pragma unroll
        for (int r = 0; r < 4; ++r) oa[nt][r] = 0.0f;

    for (int kt = 0; kt < S_; kt += 64) {
        __syncthreads();
        // ---- load K and V chunk: 64 rows x 16 float4 each ----
#pragma unroll
        for (int i = 0; i < 4; ++i) {
            const int f    = t + 256 * i;
            const int row  = f >> 4;
            const int quad = f & 15;
            const uint32_t off = SWZ128((uint32_t)(row * 128 + quad * 8));
            float4 kv = *(const float4*)&Kb[(size_t)(kt + row) * E_ + quad * 4];
            float4 vv = *(const float4*)&Vb[(size_t)(kt + row) * E_ + quad * 4];
            uint2 hh, ll;
            split4(kv, hh, ll);
            *(uint2*)(Khi + off) = hh;
            *(uint2*)(Klo + off) = ll;
            split4(vv, hh, ll);
            *(uint2*)(Vhi + off) = hh;
            *(uint2*)(Vlo + off) = ll;
        }
        __syncthreads();

        // ---- S = Q K^T (split-3), m16 x n64 per warp ----
        float s[8][4];
#pragma unroll
        for (int nt = 0; nt < 8; ++nt)
#pragma unroll
            for (int r = 0; r < 4; ++r) s[nt][r] = 0.0f;

#pragma unroll
        for (int ks = 0; ks < 4; ++ks) {
            uint32_t bh[8][2], bl[8][2];
#pragma unroll
            for (int np = 0; np < 4; ++np) {
                const uint32_t boff =
                    SWZ128((uint32_t)((np * 16 + b_row) * 128 + ks * 32 + b_kb));
                uint32_t r4[4];
                ldsm_x4(sKhi + boff, r4);
                bh[2 * np][0] = r4[0]; bh[2 * np][1] = r4[1];
                bh[2 * np + 1][0] = r4[2]; bh[2 * np + 1][1] = r4[3];
                ldsm_x4(sKlo + boff, r4);
                bl[2 * np][0] = r4[0]; bl[2 * np][1] = r4[1];
                bl[2 * np + 1][0] = r4[2]; bl[2 * np + 1][1] = r4[3];
            }
#pragma unroll
            for (int nt = 0; nt < 8; ++nt) {
                mma16816(s[nt], qh[ks], bh[nt]);
                mma16816(s[nt], qh[ks], bl[nt]);
                mma16816(s[nt], ql[ks], bh[nt]);
            }
        }

        // ---- online softmax (warp-local; rows r1=lane>>2 and r1+8) ----
#pragma unroll
        for (int nt = 0; nt < 8; ++nt)
#pragma unroll
            for (int r = 0; r < 4; ++r) s[nt][r] *= scale;

        float mx0 = -INFINITY, mx1 = -INFINITY;
#pragma unroll
        for (int nt = 0; nt < 8; ++nt) {
            mx0 = fmaxf(mx0, fmaxf(s[nt][0], s[nt][1]));
            mx1 = fmaxf(mx1, fmaxf(s[nt][2], s[nt][3]));
        }
        mx0 = fmaxf(mx0, __shfl_xor_sync(0xffffffffu, mx0, 1));
        mx0 = fmaxf(mx0, __shfl_xor_sync(0xffffffffu, mx0, 2));
        mx1 = fmaxf(mx1, __shfl_xor_sync(0xffffffffu, mx1, 1));
        mx1 = fmaxf(mx1, __shfl_xor_sync(0xffffffffu, mx1, 2));

        const float mn0 = fmaxf(m0, mx0);
        const float mn1 = fmaxf(m1, mx1);
        const float al0 = __expf(m0 - mn0);
        const float al1 = __expf(m1 - mn1);

        float rs0 = 0.0f, rs1 = 0.0f;
#pragma unroll
        for (int nt = 0; nt < 8; ++nt) {
            float p0 = __expf(s[nt][0] - mn0);
            float p1 = __expf(s[nt][1] - mn0);
            float p2 = __expf(s[nt][2] - mn1);
            float p3 = __expf(s[nt][3] - mn1);
            s[nt][0] = p0; s[nt][1] = p1; s[nt][2] = p2; s[nt][3] = p3;
            rs0 += p0 + p1;
            rs1 += p2 + p3;
        }
        rs0 += __shfl_xor_sync(0xffffffffu, rs0, 1);
        rs0 += __shfl_xor_sync(0xffffffffu, rs0, 2);
        rs1 += __shfl_xor_sync(0xffffffffu, rs1, 1);
        rs1 += __shfl_xor_sync(0xffffffffu, rs1, 2);

        l0 = l0 * al0 + rs0;  m0 = mn0;
        l1 = l1 * al1 + rs1;  m1 = mn1;
#pragma unroll
        for (int nt = 0; nt < 8; ++nt) {
            oa[nt][0] *= al0; oa[nt][1] *= al0;
            oa[nt][2] *= al1; oa[nt][3] *= al1;
        }

        // ---- O += P V (split-3); P repacked C-frag -> A-frag in registers ----
#pragma unroll
        for (int ks = 0; ks < 4; ++ks) {
            uint32_t pah[4], pal[4];
            split2(s[2 * ks][0],     s[2 * ks][1],     pah[0], pal[0]);
            split2(s[2 * ks][2],     s[2 * ks][3],     pah[1], pal[1]);
            split2(s[2 * ks + 1][0], s[2 * ks + 1][1], pah[2], pal[2]);
            split2(s[2 * ks + 1][2], s[2 * ks + 1][3], pah[3], pal[3]);

            uint32_t vh[8][2], vl[8][2];
#pragma unroll
            for (int dp = 0; dp < 4; ++dp) {
                const uint32_t voff =
                    SWZ128((uint32_t)((ks * 16 + v_row) * 128 + dp * 32 + v_db));
                uint32_t r4[4];
                ldsm_x4_t(sVhi + voff, r4);
                vh[2 * dp][0] = r4[0]; vh[2 * dp][1] = r4[1];
                vh[2 * dp + 1][0] = r4[2]; vh[2 * dp + 1][1] = r4[3];
                ldsm_x4_t(sVlo + voff, r4);
                vl[2 * dp][0] = r4[0]; vl[2 * dp][1] = r4[1];
                vl[2 * dp + 1][0] = r4[2]; vl[2 * dp + 1][1] = r4[3];
            }
#pragma unroll
            for (int nt = 0; nt < 8; ++nt) {
                mma16816(oa[nt], pah, vh[nt]);
                mma16816(oa[nt], pah, vl[nt]);
                mma16816(oa[nt], pal, vh[nt]);
            }
        }
    }

    // ---- epilogue ----
    const float inv0 = 1.0f / l0;
    const float inv1 = 1.0f / l1;
    const int r0g = q0 + wid * 16 + (lane >> 2);
    float* Ob = O + base;
#pragma unroll
    for (int nt = 0; nt < 8; ++nt) {
        const int col = nt * 8 + 2 * (lane & 3);
        float2 v0, v1;
        v0.x = oa[nt][0] * inv0; v0.y = oa[nt][1] * inv0;
        v1.x = oa[nt][2] * inv1; v1.y = oa[nt][3] * inv1;
        *(float2*)&Ob[(size_t)r0g * E_ + col]       = v0;
        *(float2*)&Ob[(size_t)(r0g + 8) * E_ + col] = v1;
    }
}

// ---------------------------------------------------------------------------
// Launch
// ---------------------------------------------------------------------------
extern "C" void kernel_launch(void* const* d_in, const int* in_sizes, int n_in,
                              void* d_out, int out_size)
{
    (void)in_sizes; (void)n_in; (void)out_size;

    const float* q     = (const float*)d_in[0];
    const float* k     = (const float*)d_in[1];
    const float* v     = (const float*)d_in[2];
    const float* w_in  = (const float*)d_in[3];
    const float* b_in  = (const float*)d_in[4];
    const float* w_out = (const float*)d_in[5];
    const float* b_out = (const float*)d_in[6];
    float* out = (float*)d_out;

    float *gq, *gk, *gv, *ga;
    cudaGetSymbolAddress((void**)&gq, g_q);
    cudaGetSymbolAddress((void**)&gk, g_k);
    cudaGetSymbolAddress((void**)&gv, g_v);
    cudaGetSymbolAddress((void**)&ga, g_attn);

    cudaFuncSetAttribute(gemm_tc,
                         cudaFuncAttributeMaxDynamicSharedMemorySize, GEMM_SMEM);
    cudaFuncSetAttribute(flash_tc,
                         cudaFuncAttributeMaxDynamicSharedMemorySize, FA_SMEM);

    dim3 gg(E_ / 128, MTOT / 128);   // (8, 32)

    gemm_tc<<<gg, 256, GEMM_SMEM>>>(q, w_in,                       b_in,          gq, E_, E_);
    gemm_tc<<<gg, 256, GEMM_SMEM>>>(k, w_in + (size_t)E_ * E_,     b_in + E_,     gk, E_, E_);
    gemm_tc<<<gg, 256, GEMM_SMEM>>>(v, w_in + (size_t)2 * E_ * E_, b_in + 2 * E_, gv, E_, E_);

    dim3 fg(S_ / 128, H_, B_);       // (16, 16, 2)
    flash_tc<<<fg, 256, FA_SMEM>>>(gq, gk, gv, ga);

    gemm_tc<<<gg, 256, GEMM_SMEM>>>(ga, w_out, b_out, out, E_, E_);
}

// round 9
// speedup vs baseline: 3.0125x; 1.1016x over previous
#include <cuda_runtime.h>
#include <cuda_bf16.h>
#include <cstdint>
#include <math.h>

#define B_   2
#define S_   2048
#define E_   1024
#define H_   16
#define D_   64
#define MTOT (B_ * S_)   // 4096

// ---- prepacked bf16 scratch (hi/lo split), __device__ globals ----
__device__ __nv_bfloat16 g_inq_h[MTOT * E_], g_inq_l[MTOT * E_];
__device__ __nv_bfloat16 g_ink_h[MTOT * E_], g_ink_l[MTOT * E_];
__device__ __nv_bfloat16 g_inv_h[MTOT * E_], g_inv_l[MTOT * E_];
__device__ __nv_bfloat16 g_win_h[3 * E_ * E_], g_win_l[3 * E_ * E_];
__device__ __nv_bfloat16 g_wout_h[E_ * E_], g_wout_l[E_ * E_];
__device__ __nv_bfloat16 g_pq_h[MTOT * E_], g_pq_l[MTOT * E_];
__device__ __nv_bfloat16 g_pk_h[MTOT * E_], g_pk_l[MTOT * E_];
__device__ __nv_bfloat16 g_pv_h[MTOT * E_], g_pv_l[MTOT * E_];
__device__ __nv_bfloat16 g_at_h[MTOT * E_], g_at_l[MTOT * E_];

__device__ __forceinline__ uint32_t smem_u32(const void* p) {
    uint32_t a;
    asm("{ .reg .u64 t; cvta.to.shared.u64 t, %1; cvt.u32.u64 %0, t; }"
        : "=r"(a) : "l"(p));
    return a;
}

#define SWZ128(off) ((off) ^ (((off) >> 3) & 0x70))

__device__ __forceinline__ void cp_async16(uint32_t dst, const void* src) {
    asm volatile("cp.async.cg.shared.global [%0], [%1], 16;"
                 :: "r"(dst), "l"(src));
}
#define CP_COMMIT() asm volatile("cp.async.commit_group;" ::: "memory")
#define CP_WAIT(n)  asm volatile("cp.async.wait_group %0;" :: "n"(n) : "memory")

__device__ __forceinline__ void ldsm_x4(uint32_t addr, uint32_t* r) {
    asm volatile(
        "ldmatrix.sync.aligned.m8n8.x4.shared.b16 {%0,%1,%2,%3}, [%4];"
        : "=r"(r[0]), "=r"(r[1]), "=r"(r[2]), "=r"(r[3]) : "r"(addr));
}
__device__ __forceinline__ void ldsm_x4_t(uint32_t addr, uint32_t* r) {
    asm volatile(
        "ldmatrix.sync.aligned.m8n8.x4.trans.shared.b16 {%0,%1,%2,%3}, [%4];"
        : "=r"(r[0]), "=r"(r[1]), "=r"(r[2]), "=r"(r[3]) : "r"(addr));
}
__device__ __forceinline__ void mma16816(float* d, const uint32_t* a, const uint32_t* b) {
    asm volatile(
        "mma.sync.aligned.m16n8k16.row.col.f32.bf16.bf16.f32 "
        "{%0,%1,%2,%3}, {%4,%5,%6,%7}, {%8,%9}, {%0,%1,%2,%3};"
        : "+f"(d[0]), "+f"(d[1]), "+f"(d[2]), "+f"(d[3])
        : "r"(a[0]), "r"(a[1]), "r"(a[2]), "r"(a[3]), "r"(b[0]), "r"(b[1]));
}

__device__ __forceinline__ void split4(float4 v, uint2& h, uint2& l)
{
    __nv_bfloat162 h01 = __floats2bfloat162_rn(v.x, v.y);
    __nv_bfloat162 h23 = __floats2bfloat162_rn(v.z, v.w);
    float2 f01 = __bfloat1622float2(h01);
    float2 f23 = __bfloat1622float2(h23);
    __nv_bfloat162 l01 = __floats2bfloat162_rn(v.x - f01.x, v.y - f01.y);
    __nv_bfloat162 l23 = __floats2bfloat162_rn(v.z - f23.x, v.w - f23.y);
    h.x = *reinterpret_cast<uint32_t*>(&h01);
    h.y = *reinterpret_cast<uint32_t*>(&h23);
    l.x = *reinterpret_cast<uint32_t*>(&l01);
    l.y = *reinterpret_cast<uint32_t*>(&l23);
}
__device__ __forceinline__ void split2(float a, float b, uint32_t& hi, uint32_t& lo)
{
    __nv_bfloat162 h = __floats2bfloat162_rn(a, b);
    float2 f = __bfloat1622float2(h);
    __nv_bfloat162 l = __floats2bfloat162_rn(a - f.x, b - f.y);
    hi = *reinterpret_cast<uint32_t*>(&h);
    lo = *reinterpret_cast<uint32_t*>(&l);
}

// ===========================================================================
// Prepack: fp32 -> (hi, lo) bf16, elementwise float4
// ===========================================================================
__global__ __launch_bounds__(256) void split_kernel(
    const float* __restrict__ src, __nv_bfloat16* __restrict__ hi,
    __nv_bfloat16* __restrict__ lo, int n4)
{
    int i = blockIdx.x * 256 + threadIdx.x;
    if (i < n4) {
        float4 v = ((const float4*)src)[i];
        uint2 h, l;
        split4(v, h, l);
        ((uint2*)hi)[i] = h;
        ((uint2*)lo)[i] = l;
    }
}

// ===========================================================================
// GEMM (NT), prepacked bf16 operands, cp.async 2-stage pipeline.
// Tile 128x128, BK=64. 8 warps: wm=(wid&1)*64, wn=(wid>>1)*32.
// Stage: Ah[16K] Al[16K] Bh[16K] Bl[16K]; 2 stages = 128KB smem.
// BF16OUT: write split bf16 (Yh/Yl); else fp32 (Yf), bias added either way.
// ===========================================================================
#define GEMM_SMEM (2 * 65536)

template<bool BF16OUT>
__global__ __launch_bounds__(256) void gemm_pk(
    const __nv_bfloat16* __restrict__ Xh, const __nv_bfloat16* __restrict__ Xl,
    const __nv_bfloat16* __restrict__ Wh, const __nv_bfloat16* __restrict__ Wl,
    const float* __restrict__ bias,
    float* __restrict__ Yf, __nv_bfloat16* __restrict__ Yh,
    __nv_bfloat16* __restrict__ Yl, int K, int N)
{
    extern __shared__ char smem[];
    const uint32_t sb = smem_u32(smem);

    const int t    = threadIdx.x;
    const int wid  = t >> 5;
    const int lane = t & 31;
    const int bm   = blockIdx.y * 128;
    const int bn   = blockIdx.x * 128;
    const int wm   = (wid & 1) * 64;
    const int wn   = (wid >> 1) * 32;

    float acc[4][4][4];
#pragma unroll
    for (int i = 0; i < 4; i++)
#pragma unroll
        for (int j = 0; j < 4; j++)
#pragma unroll
            for (int r = 0; r < 4; r++) acc[i][j][r] = 0.0f;

    const int a_row = (lane & 15);
    const int a_kb  = ((lane >> 4) & 1) * 16;
    const int b_row = ((lane >> 4) & 1) * 8 + (lane & 7);
    const int b_kb  = ((lane >> 3) & 1) * 16;

    const int nchunks = K / 64;   // 16

    // stage loader: 128 rows x 8 chunks of 16B per array
    auto load_stage = [&](int c, int s) {
        const int k0 = c * 64;
        const uint32_t st = sb + s * 65536;
#pragma unroll
        for (int i = 0; i < 4; ++i) {
            const int f   = t + 256 * i;      // 0..1023
            const int row = f >> 3;
            const int ch  = (f & 7) * 8;      // bf16 elems
            const uint32_t off = SWZ128((uint32_t)(row * 128 + ch * 2));
            const size_t xo = (size_t)(bm + row) * K + k0 + ch;
            const size_t wo = (size_t)(bn + row) * K + k0 + ch;
            cp_async16(st + off,         &Xh[xo]);
            cp_async16(st + 16384 + off, &Xl[xo]);
            cp_async16(st + 32768 + off, &Wh[wo]);
            cp_async16(st + 49152 + off, &Wl[wo]);
        }
        CP_COMMIT();
    };

    load_stage(0, 0);
    for (int c = 0; c < nchunks; ++c) {
        if (c + 1 < nchunks) { load_stage(c + 1, (c + 1) & 1); CP_WAIT(1); }
        else                 { CP_WAIT(0); }
        __syncthreads();

        const uint32_t st  = sb + (c & 1) * 65536;
        const uint32_t sAh = st, sAl = st + 16384, sBh = st + 32768, sBl = st + 49152;
#pragma unroll
        for (int ks = 0; ks < 4; ++ks) {
            const int kb = ks * 32;
            uint32_t bh[4][2], bl[4][2];
#pragma unroll
            for (int np = 0; np < 2; ++np) {
                const uint32_t boff =
                    SWZ128((uint32_t)((wn + np * 16 + b_row) * 128 + kb + b_kb));
                uint32_t r4[4];
                ldsm_x4(sBh + boff, r4);
                bh[2 * np][0] = r4[0]; bh[2 * np][1] = r4[1];
                bh[2 * np + 1][0] = r4[2]; bh[2 * np + 1][1] = r4[3];
                ldsm_x4(sBl + boff, r4);
                bl[2 * np][0] = r4[0]; bl[2 * np][1] = r4[1];
                bl[2 * np + 1][0] = r4[2]; bl[2 * np + 1][1] = r4[3];
            }
#pragma unroll
            for (int mt = 0; mt < 4; ++mt) {
                const uint32_t aoff =
                    SWZ128((uint32_t)((wm + mt * 16 + a_row) * 128 + kb + a_kb));
                uint32_t ah[4], al[4];
                ldsm_x4(sAh + aoff, ah);
                ldsm_x4(sAl + aoff, al);
#pragma unroll
                for (int nt = 0; nt < 4; ++nt) {
                    mma16816(acc[mt][nt], ah, bh[nt]);
                    mma16816(acc[mt][nt], ah, bl[nt]);
                    mma16816(acc[mt][nt], al, bh[nt]);
                }
            }
        }
        __syncthreads();
    }

    const int cr = lane >> 2;
    const int cc = (lane & 3) * 2;
#pragma unroll
    for (int mt = 0; mt < 4; ++mt) {
        const int row0 = bm + wm + mt * 16 + cr;
#pragma unroll
        for (int nt = 0; nt < 4; ++nt) {
            const int col = bn + wn + nt * 8 + cc;
            const float2 bv = *(const float2*)&bias[col];
            float a0 = acc[mt][nt][0] + bv.x, a1 = acc[mt][nt][1] + bv.y;
            float a2 = acc[mt][nt][2] + bv.x, a3 = acc[mt][nt][3] + bv.y;
            if (BF16OUT) {
                uint32_t h0, l0, h1, l1;
                split2(a0, a1, h0, l0);
                split2(a2, a3, h1, l1);
                *(uint32_t*)&Yh[(size_t)row0 * N + col]       = h0;
                *(uint32_t*)&Yl[(size_t)row0 * N + col]       = l0;
                *(uint32_t*)&Yh[(size_t)(row0 + 8) * N + col] = h1;
                *(uint32_t*)&Yl[(size_t)(row0 + 8) * N + col] = l1;
            } else {
                float2 v0 = {a0, a1}, v1 = {a2, a3};
                *(float2*)&Yf[(size_t)row0 * N + col]       = v0;
                *(float2*)&Yf[(size_t)(row0 + 8) * N + col] = v1;
            }
        }
    }
}

// ===========================================================================
// Flash attention, prepacked bf16, cp.async double-buffered K/V.
// CTA: 128 q-rows, 8 warps x 16 rows, Bc=64. Q frags direct from gmem.
// Stage: Kh[8K] Kl[8K] Vh[8K] Vl[8K]; 2 stages = 64KB smem.
// ===========================================================================
#define FA_SMEM (2 * 32768)

__global__ __launch_bounds__(256) void flash_pk(
    const __nv_bfloat16* __restrict__ Qh, const __nv_bfloat16* __restrict__ Ql,
    const __nv_bfloat16* __restrict__ Kh, const __nv_bfloat16* __restrict__ Kl,
    const __nv_bfloat16* __restrict__ Vh, const __nv_bfloat16* __restrict__ Vl,
    __nv_bfloat16* __restrict__ Oh, __nv_bfloat16* __restrict__ Ol)
{
    extern __shared__ char smem[];
    const uint32_t sb = smem_u32(smem);

    const int t    = threadIdx.x;
    const int wid  = t >> 5;
    const int lane = t & 31;
    const int q0   = blockIdx.x * 128;
    const int h    = blockIdx.y;
    const int b    = blockIdx.z;
    const float scale = 0.125f;

    const size_t base = (size_t)b * S_ * E_ + (size_t)h * D_;

    // ---- Q fragments straight from gmem (A-frag layout is gmem-linear) ----
    const int qrow = q0 + wid * 16 + (lane >> 2);
    const int qcol = (lane & 3) * 2;
    uint32_t qh[4][4], ql[4][4];
#pragma unroll
    for (int ks = 0; ks < 4; ++ks) {
        const size_t o00 = base + (size_t)qrow * E_ + ks * 16 + qcol;
        qh[ks][0] = *(const uint32_t*)&Qh[o00];
        qh[ks][1] = *(const uint32_t*)&Qh[o00 + 8 * E_];
        qh[ks][2] = *(const uint32_t*)&Qh[o00 + 8];
        qh[ks][3] = *(const uint32_t*)&Qh[o00 + 8 * E_ + 8];
        ql[ks][0] = *(const uint32_t*)&Ql[o00];
        ql[ks][1] = *(const uint32_t*)&Ql[o00 + 8 * E_];
        ql[ks][2] = *(const uint32_t*)&Ql[o00 + 8];
        ql[ks][3] = *(const uint32_t*)&Ql[o00 + 8 * E_ + 8];
    }

    const int b_row = ((lane >> 4) & 1) * 8 + (lane & 7);
    const int b_kb  = ((lane >> 3) & 1) * 16;
    const int v_row = ((lane >> 3) & 1) * 8 + (lane & 7);
    const int v_db  = ((lane >> 4) & 1) * 16;

    float m0 = -INFINITY, m1 = -INFINITY, l0 = 0.0f, l1 = 0.0f;
    float oa[8][4];
#pragma unroll
    for (int nt = 0; nt < 8; ++nt)
#pragma unroll
        for (int r = 0; r < 4; ++r) oa[nt][r] = 0.0f;

    // stage loader: 64 rows x 8 chunks of 16B per array
    auto load_stage = [&](int kt, int s) {
        const uint32_t st = sb + s * 32768;
#pragma unroll
        for (int i = 0; i < 2; ++i) {
            const int f   = t + 256 * i;      // 0..511
            const int row = f >> 3;
            const int ch  = (f & 7) * 8;
            const uint32_t off = SWZ128((uint32_t)(row * 128 + ch * 2));
            const size_t go = base + (size_t)(kt + row) * E_ + ch;
            cp_async16(st + off,         &Kh[go]);
            cp_async16(st + 8192 + off,  &Kl[go]);
            cp_async16(st + 16384 + off, &Vh[go]);
            cp_async16(st + 24576 + off, &Vl[go]);
        }
        CP_COMMIT();
    };

    const int niter = S_ / 64;   // 32
    load_stage(0, 0);
    for (int it = 0; it < niter; ++it) {
        if (it + 1 < niter) { load_stage((it + 1) * 64, (it + 1) & 1); CP_WAIT(1); }
        else                { CP_WAIT(0); }
        __syncthreads();

        const uint32_t st  = sb + (it & 1) * 32768;
        const uint32_t sKh = st, sKl = st + 8192, sVh = st + 16384, sVl = st + 24576;

        // ---- S = Q K^T (split-3) ----
        float s[8][4];
#pragma unroll
        for (int nt = 0; nt < 8; ++nt)
#pragma unroll
            for (int r = 0; r < 4; ++r) s[nt][r] = 0.0f;

#pragma unroll
        for (int ks = 0; ks < 4; ++ks) {
            uint32_t bh[8][2], bl[8][2];
#pragma unroll
            for (int np = 0; np < 4; ++np) {
                const uint32_t boff =
                    SWZ128((uint32_t)((np * 16 + b_row) * 128 + ks * 32 + b_kb));
                uint32_t r4[4];
                ldsm_x4(sKh + boff, r4);
                bh[2 * np][0] = r4[0]; bh[2 * np][1] = r4[1];
                bh[2 * np + 1][0] = r4[2]; bh[2 * np + 1][1] = r4[3];
                ldsm_x4(sKl + boff, r4);
                bl[2 * np][0] = r4[0]; bl[2 * np][1] = r4[1];
                bl[2 * np + 1][0] = r4[2]; bl[2 * np + 1][1] = r4[3];
            }
#pragma unroll
            for (int nt = 0; nt < 8; ++nt) {
                mma16816(s[nt], qh[ks], bh[nt]);
                mma16816(s[nt], qh[ks], bl[nt]);
                mma16816(s[nt], ql[ks], bh[nt]);
            }
        }

        // ---- online softmax (warp-local) ----
#pragma unroll
        for (int nt = 0; nt < 8; ++nt)
#pragma unroll
            for (int r = 0; r < 4; ++r) s[nt][r] *= scale;

        float mx0 = -INFINITY, mx1 = -INFINITY;
#pragma unroll
        for (int nt = 0; nt < 8; ++nt) {
            mx0 = fmaxf(mx0, fmaxf(s[nt][0], s[nt][1]));
            mx1 = fmaxf(mx1, fmaxf(s[nt][2], s[nt][3]));
        }
        mx0 = fmaxf(mx0, __shfl_xor_sync(0xffffffffu, mx0, 1));
        mx0 = fmaxf(mx0, __shfl_xor_sync(0xffffffffu, mx0, 2));
        mx1 = fmaxf(mx1, __shfl_xor_sync(0xffffffffu, mx1, 1));
        mx1 = fmaxf(mx1, __shfl_xor_sync(0xffffffffu, mx1, 2));

        const float mn0 = fmaxf(m0, mx0);
        const float mn1 = fmaxf(m1, mx1);
        const float al0 = __expf(m0 - mn0);
        const float al1 = __expf(m1 - mn1);

        float rs0 = 0.0f, rs1 = 0.0f;
#pragma unroll
        for (int nt = 0; nt < 8; ++nt) {
            float p0 = __expf(s[nt][0] - mn0);
            float p1 = __expf(s[nt][1] - mn0);
            float p2 = __expf(s[nt][2] - mn1);
            float p3 = __expf(s[nt][3] - mn1);
            s[nt][0] = p0; s[nt][1] = p1; s[nt][2] = p2; s[nt][3] = p3;
            rs0 += p0 + p1;
            rs1 += p2 + p3;
        }
        rs0 += __shfl_xor_sync(0xffffffffu, rs0, 1);
        rs0 += __shfl_xor_sync(0xffffffffu, rs0, 2);
        rs1 += __shfl_xor_sync(0xffffffffu, rs1, 1);
        rs1 += __shfl_xor_sync(0xffffffffu, rs1, 2);

        l0 = l0 * al0 + rs0;  m0 = mn0;
        l1 = l1 * al1 + rs1;  m1 = mn1;
#pragma unroll
        for (int nt = 0; nt < 8; ++nt) {
            oa[nt][0] *= al0; oa[nt][1] *= al0;
            oa[nt][2] *= al1; oa[nt][3] *= al1;
        }

        // ---- O += P V (split-3) ----
#pragma unroll
        for (int ks = 0; ks < 4; ++ks) {
            uint32_t pah[4], pal[4];
            split2(s[2 * ks][0],     s[2 * ks][1],     pah[0], pal[0]);
            split2(s[2 * ks][2],     s[2 * ks][3],     pah[1], pal[1]);
            split2(s[2 * ks + 1][0], s[2 * ks + 1][1], pah[2], pal[2]);
            split2(s[2 * ks + 1][2], s[2 * ks + 1][3], pah[3], pal[3]);

            uint32_t vh[8][2], vl[8][2];
#pragma unroll
            for (int dp = 0; dp < 4; ++dp) {
                const uint32_t voff =
                    SWZ128((uint32_t)((ks * 16 + v_row) * 128 + dp * 32 + v_db));
                uint32_t r4[4];
                ldsm_x4_t(sVh + voff, r4);
                vh[2 * dp][0] = r4[0]; vh[2 * dp][1] = r4[1];
                vh[2 * dp + 1][0] = r4[2]; vh[2 * dp + 1][1] = r4[3];
                ldsm_x4_t(sVl + voff, r4);
                vl[2 * dp][0] = r4[0]; vl[2 * dp][1] = r4[1];
                vl[2 * dp + 1][0] = r4[2]; vl[2 * dp + 1][1] = r4[3];
            }
#pragma unroll
            for (int nt = 0; nt < 8; ++nt) {
                mma16816(oa[nt], pah, vh[nt]);
                mma16816(oa[nt], pah, vl[nt]);
                mma16816(oa[nt], pal, vh[nt]);
            }
        }
        __syncthreads();
    }

    // ---- epilogue: normalized output as split bf16 ----
    const float inv0 = 1.0f / l0;
    const float inv1 = 1.0f / l1;
    const int r0g = q0 + wid * 16 + (lane >> 2);
#pragma unroll
    for (int nt = 0; nt < 8; ++nt) {
        const int col = nt * 8 + 2 * (lane & 3);
        uint32_t h0, lo0, h1, lo1;
        split2(oa[nt][0] * inv0, oa[nt][1] * inv0, h0, lo0);
        split2(oa[nt][2] * inv1, oa[nt][3] * inv1, h1, lo1);
        const size_t o0 = base + (size_t)r0g * E_ + col;
        *(uint32_t*)&Oh[o0]           = h0;
        *(uint32_t*)&Ol[o0]           = lo0;
        *(uint32_t*)&Oh[o0 + 8 * E_]  = h1;
        *(uint32_t*)&Ol[o0 + 8 * E_]  = lo1;
    }
}

// ---------------------------------------------------------------------------
// Launch
// ---------------------------------------------------------------------------
extern "C" void kernel_launch(void* const* d_in, const int* in_sizes, int n_in,
                              void* d_out, int out_size)
{
    (void)in_sizes; (void)n_in; (void)out_size;

    const float* q     = (const float*)d_in[0];
    const float* k     = (const float*)d_in[1];
    const float* v     = (const float*)d_in[2];
    const float* w_in  = (const float*)d_in[3];
    const float* b_in  = (const float*)d_in[4];
    const float* w_out = (const float*)d_in[5];
    const float* b_out = (const float*)d_in[6];
    float* out = (float*)d_out;

    __nv_bfloat16 *inq_h, *inq_l, *ink_h, *ink_l, *inv_h, *inv_l;
    __nv_bfloat16 *win_h, *win_l, *wout_h, *wout_l;
    __nv_bfloat16 *pq_h, *pq_l, *pk_h, *pk_l, *pv_h, *pv_l, *at_h, *at_l;
    cudaGetSymbolAddress((void**)&inq_h, g_inq_h);  cudaGetSymbolAddress((void**)&inq_l, g_inq_l);
    cudaGetSymbolAddress((void**)&ink_h, g_ink_h);  cudaGetSymbolAddress((void**)&ink_l, g_ink_l);
    cudaGetSymbolAddress((void**)&inv_h, g_inv_h);  cudaGetSymbolAddress((void**)&inv_l, g_inv_l);
    cudaGetSymbolAddress((void**)&win_h, g_win_h);  cudaGetSymbolAddress((void**)&win_l, g_win_l);
    cudaGetSymbolAddress((void**)&wout_h, g_wout_h); cudaGetSymbolAddress((void**)&wout_l, g_wout_l);
    cudaGetSymbolAddress((void**)&pq_h, g_pq_h);    cudaGetSymbolAddress((void**)&pq_l, g_pq_l);
    cudaGetSymbolAddress((void**)&pk_h, g_pk_h);    cudaGetSymbolAddress((void**)&pk_l, g_pk_l);
    cudaGetSymbolAddress((void**)&pv_h, g_pv_h);    cudaGetSymbolAddress((void**)&pv_l, g_pv_l);
    cudaGetSymbolAddress((void**)&at_h, g_at_h);    cudaGetSymbolAddress((void**)&at_l, g_at_l);

    cudaFuncSetAttribute(gemm_pk<true>,
                         cudaFuncAttributeMaxDynamicSharedMemorySize, GEMM_SMEM);
    cudaFuncSetAttribute(gemm_pk<false>,
                         cudaFuncAttributeMaxDynamicSharedMemorySize, GEMM_SMEM);
    cudaFuncSetAttribute(flash_pk,
                         cudaFuncAttributeMaxDynamicSharedMemorySize, FA_SMEM);

    // ---- prepack ----
    const int n4_io = MTOT * E_ / 4;       // 1048576
    const int n4_wi = 3 * E_ * E_ / 4;     // 786432
    const int n4_wo = E_ * E_ / 4;         // 262144
    split_kernel<<<n4_io / 256, 256>>>(q, inq_h, inq_l, n4_io);
    split_kernel<<<n4_io / 256, 256>>>(k, ink_h, ink_l, n4_io);
    split_kernel<<<n4_io / 256, 256>>>(v, inv_h, inv_l, n4_io);
    split_kernel<<<n4_wi / 256, 256>>>(w_in, win_h, win_l, n4_wi);
    split_kernel<<<n4_wo / 256, 256>>>(w_out, wout_h, wout_l, n4_wo);

    dim3 gg(E_ / 128, MTOT / 128);   // (8, 32)
    gemm_pk<true><<<gg, 256, GEMM_SMEM>>>(inq_h, inq_l, win_h, win_l,
        b_in, nullptr, pq_h, pq_l, E_, E_);
    gemm_pk<true><<<gg, 256, GEMM_SMEM>>>(ink_h, ink_l,
        win_h + (size_t)E_ * E_, win_l + (size_t)E_ * E_,
        b_in + E_, nullptr, pk_h, pk_l, E_, E_);
    gemm_pk<true><<<gg, 256, GEMM_SMEM>>>(inv_h, inv_l,
        win_h + (size_t)2 * E_ * E_, win_l + (size_t)2 * E_ * E_,
        b_in + 2 * E_, nullptr, pv_h, pv_l, E_, E_);

    dim3 fg(S_ / 128, H_, B_);       // (16, 16, 2)
    flash_pk<<<fg, 256, FA_SMEM>>>(pq_h, pq_l, pk_h, pk_l, pv_h, pv_l, at_h, at_l);

    gemm_pk<false><<<gg, 256, GEMM_SMEM>>>(at_h, at_l, wout_h, wout_l,
        b_out, out, nullptr, nullptr, E_, E_);
}

// round 10
// speedup vs baseline: 3.4444x; 1.1434x over previous
#include <cuda_runtime.h>
#include <cuda_bf16.h>
#include <cstdint>
#include <math.h>

#define B_   2
#define S_   2048
#define E_   1024
#define H_   16
#define D_   64
#define MTOT (B_ * S_)   // 4096

// ---- prepacked bf16 scratch (hi/lo split), __device__ globals ----
__device__ __nv_bfloat16 g_inq_h[MTOT * E_], g_inq_l[MTOT * E_];
__device__ __nv_bfloat16 g_ink_h[MTOT * E_], g_ink_l[MTOT * E_];
__device__ __nv_bfloat16 g_inv_h[MTOT * E_], g_inv_l[MTOT * E_];
__device__ __nv_bfloat16 g_win_h[3 * E_ * E_], g_win_l[3 * E_ * E_];
__device__ __nv_bfloat16 g_wout_h[E_ * E_], g_wout_l[E_ * E_];
__device__ __nv_bfloat16 g_pq_h[MTOT * E_], g_pq_l[MTOT * E_];
__device__ __nv_bfloat16 g_pk_h[MTOT * E_], g_pk_l[MTOT * E_];
__device__ __nv_bfloat16 g_pv_h[MTOT * E_], g_pv_l[MTOT * E_];
__device__ __nv_bfloat16 g_at_h[MTOT * E_], g_at_l[MTOT * E_];

__device__ __forceinline__ uint32_t smem_u32(const void* p) {
    uint32_t a;
    asm("{ .reg .u64 t; cvta.to.shared.u64 t, %1; cvt.u32.u64 %0, t; }"
        : "=r"(a) : "l"(p));
    return a;
}

#define SWZ128(off) ((off) ^ (((off) >> 3) & 0x70))

__device__ __forceinline__ void cp_async16(uint32_t dst, const void* src) {
    asm volatile("cp.async.cg.shared.global [%0], [%1], 16;"
                 :: "r"(dst), "l"(src));
}
#define CP_COMMIT() asm volatile("cp.async.commit_group;" ::: "memory")
#define CP_WAIT(n)  asm volatile("cp.async.wait_group %0;" :: "n"(n) : "memory")

__device__ __forceinline__ void ldsm_x4(uint32_t addr, uint32_t* r) {
    asm volatile(
        "ldmatrix.sync.aligned.m8n8.x4.shared.b16 {%0,%1,%2,%3}, [%4];"
        : "=r"(r[0]), "=r"(r[1]), "=r"(r[2]), "=r"(r[3]) : "r"(addr));
}
__device__ __forceinline__ void ldsm_x4_t(uint32_t addr, uint32_t* r) {
    asm volatile(
        "ldmatrix.sync.aligned.m8n8.x4.trans.shared.b16 {%0,%1,%2,%3}, [%4];"
        : "=r"(r[0]), "=r"(r[1]), "=r"(r[2]), "=r"(r[3]) : "r"(addr));
}
__device__ __forceinline__ void mma16816(float* d, const uint32_t* a, const uint32_t* b) {
    asm volatile(
        "mma.sync.aligned.m16n8k16.row.col.f32.bf16.bf16.f32 "
        "{%0,%1,%2,%3}, {%4,%5,%6,%7}, {%8,%9}, {%0,%1,%2,%3};"
        : "+f"(d[0]), "+f"(d[1]), "+f"(d[2]), "+f"(d[3])
        : "r"(a[0]), "r"(a[1]), "r"(a[2]), "r"(a[3]), "r"(b[0]), "r"(b[1]));
}

__device__ __forceinline__ void split4(float4 v, uint2& h, uint2& l)
{
    __nv_bfloat162 h01 = __floats2bfloat162_rn(v.x, v.y);
    __nv_bfloat162 h23 = __floats2bfloat162_rn(v.z, v.w);
    float2 f01 = __bfloat1622float2(h01);
    float2 f23 = __bfloat1622float2(h23);
    __nv_bfloat162 l01 = __floats2bfloat162_rn(v.x - f01.x, v.y - f01.y);
    __nv_bfloat162 l23 = __floats2bfloat162_rn(v.z - f23.x, v.w - f23.y);
    h.x = *reinterpret_cast<uint32_t*>(&h01);
    h.y = *reinterpret_cast<uint32_t*>(&h23);
    l.x = *reinterpret_cast<uint32_t*>(&l01);
    l.y = *reinterpret_cast<uint32_t*>(&l23);
}
__device__ __forceinline__ void split2(float a, float b, uint32_t& hi, uint32_t& lo)
{
    __nv_bfloat162 h = __floats2bfloat162_rn(a, b);
    float2 f = __bfloat1622float2(h);
    __nv_bfloat162 l = __floats2bfloat162_rn(a - f.x, b - f.y);
    hi = *reinterpret_cast<uint32_t*>(&h);
    lo = *reinterpret_cast<uint32_t*>(&l);
}

// ===========================================================================
// Prepack: all 5 splits in one launch (grid.y = segment)
// ===========================================================================
struct SplitJobs {
    const float* src[5];
    __nv_bfloat16* hi[5];
    __nv_bfloat16* lo[5];
    int n4[5];
};

__global__ __launch_bounds__(256) void split_all(SplitJobs j)
{
    const int seg = blockIdx.y;
    const int i = blockIdx.x * 256 + threadIdx.x;
    if (i < j.n4[seg]) {
        float4 v = ((const float4*)j.src[seg])[i];
        uint2 h, l;
        split4(v, h, l);
        ((uint2*)j.hi[seg])[i] = h;
        ((uint2*)j.lo[seg])[i] = l;
    }
}

// ===========================================================================
// GEMM core (NT), prepacked bf16, cp.async 2-stage, 128x128 tile, BK=64.
// ===========================================================================
#define GEMM_SMEM (2 * 65536)

template<bool BF16OUT>
__device__ __forceinline__ void gemm_body(
    const __nv_bfloat16* __restrict__ Xh, const __nv_bfloat16* __restrict__ Xl,
    const __nv_bfloat16* __restrict__ Wh, const __nv_bfloat16* __restrict__ Wl,
    const float* __restrict__ bias,
    float* __restrict__ Yf, __nv_bfloat16* __restrict__ Yh,
    __nv_bfloat16* __restrict__ Yl, int K, int N, char* smem)
{
    const uint32_t sb = smem_u32(smem);

    const int t    = threadIdx.x;
    const int wid  = t >> 5;
    const int lane = t & 31;
    const int bm   = blockIdx.y * 128;
    const int bn   = blockIdx.x * 128;
    const int wm   = (wid & 1) * 64;
    const int wn   = (wid >> 1) * 32;

    float acc[4][4][4];
#pragma unroll
    for (int i = 0; i < 4; i++)
#pragma unroll
        for (int j = 0; j < 4; j++)
#pragma unroll
            for (int r = 0; r < 4; r++) acc[i][j][r] = 0.0f;

    const int a_row = (lane & 15);
    const int a_kb  = ((lane >> 4) & 1) * 16;
    const int b_row = ((lane >> 4) & 1) * 8 + (lane & 7);
    const int b_kb  = ((lane >> 3) & 1) * 16;

    const int nchunks = K / 64;

    auto load_stage = [&](int c, int s) {
        const int k0 = c * 64;
        const uint32_t st = sb + s * 65536;
#pragma unroll
        for (int i = 0; i < 4; ++i) {
            const int f   = t + 256 * i;
            const int row = f >> 3;
            const int ch  = (f & 7) * 8;
            const uint32_t off = SWZ128((uint32_t)(row * 128 + ch * 2));
            const size_t xo = (size_t)(bm + row) * K + k0 + ch;
            const size_t wo = (size_t)(bn + row) * K + k0 + ch;
            cp_async16(st + off,         &Xh[xo]);
            cp_async16(st + 16384 + off, &Xl[xo]);
            cp_async16(st + 32768 + off, &Wh[wo]);
            cp_async16(st + 49152 + off, &Wl[wo]);
        }
        CP_COMMIT();
    };

    load_stage(0, 0);
    for (int c = 0; c < nchunks; ++c) {
        if (c + 1 < nchunks) { load_stage(c + 1, (c + 1) & 1); CP_WAIT(1); }
        else                 { CP_WAIT(0); }
        __syncthreads();

        const uint32_t st  = sb + (c & 1) * 65536;
        const uint32_t sAh = st, sAl = st + 16384, sBh = st + 32768, sBl = st + 49152;
#pragma unroll
        for (int ks = 0; ks < 4; ++ks) {
            const int kb = ks * 32;
            uint32_t bh[4][2], bl[4][2];
#pragma unroll
            for (int np = 0; np < 2; ++np) {
                const uint32_t boff =
                    SWZ128((uint32_t)((wn + np * 16 + b_row) * 128 + kb + b_kb));
                uint32_t r4[4];
                ldsm_x4(sBh + boff, r4);
                bh[2 * np][0] = r4[0]; bh[2 * np][1] = r4[1];
                bh[2 * np + 1][0] = r4[2]; bh[2 * np + 1][1] = r4[3];
                ldsm_x4(sBl + boff, r4);
                bl[2 * np][0] = r4[0]; bl[2 * np][1] = r4[1];
                bl[2 * np + 1][0] = r4[2]; bl[2 * np + 1][1] = r4[3];
            }
#pragma unroll
            for (int mt = 0; mt < 4; ++mt) {
                const uint32_t aoff =
                    SWZ128((uint32_t)((wm + mt * 16 + a_row) * 128 + kb + a_kb));
                uint32_t ah[4], al[4];
                ldsm_x4(sAh + aoff, ah);
                ldsm_x4(sAl + aoff, al);
#pragma unroll
                for (int nt = 0; nt < 4; ++nt) {
                    mma16816(acc[mt][nt], ah, bh[nt]);
                    mma16816(acc[mt][nt], ah, bl[nt]);
                    mma16816(acc[mt][nt], al, bh[nt]);
                }
            }
        }
        __syncthreads();
    }

    const int cr = lane >> 2;
    const int cc = (lane & 3) * 2;
#pragma unroll
    for (int mt = 0; mt < 4; ++mt) {
        const int row0 = bm + wm + mt * 16 + cr;
#pragma unroll
        for (int nt = 0; nt < 4; ++nt) {
            const int col = bn + wn + nt * 8 + cc;
            const float2 bv = *(const float2*)&bias[col];
            float a0 = acc[mt][nt][0] + bv.x, a1 = acc[mt][nt][1] + bv.y;
            float a2 = acc[mt][nt][2] + bv.x, a3 = acc[mt][nt][3] + bv.y;
            if (BF16OUT) {
                uint32_t h0, l0, h1, l1;
                split2(a0, a1, h0, l0);
                split2(a2, a3, h1, l1);
                *(uint32_t*)&Yh[(size_t)row0 * N + col]       = h0;
                *(uint32_t*)&Yl[(size_t)row0 * N + col]       = l0;
                *(uint32_t*)&Yh[(size_t)(row0 + 8) * N + col] = h1;
                *(uint32_t*)&Yl[(size_t)(row0 + 8) * N + col] = l1;
            } else {
                float2 v0 = {a0, a1}, v1 = {a2, a3};
                *(float2*)&Yf[(size_t)row0 * N + col]       = v0;
                *(float2*)&Yf[(size_t)(row0 + 8) * N + col] = v1;
            }
        }
    }
}

// Merged QKV projection: grid.z in {0,1,2} selects input / weight slice / output
struct QkvPtrs {
    const __nv_bfloat16* xh[3];
    const __nv_bfloat16* xl[3];
    __nv_bfloat16* yh[3];
    __nv_bfloat16* yl[3];
    const __nv_bfloat16* wh;
    const __nv_bfloat16* wl;
    const float* bias;
};

__global__ __launch_bounds__(256) void gemm_qkv(QkvPtrs p)
{
    extern __shared__ char smem[];
    const int z = blockIdx.z;
    gemm_body<true>(p.xh[z], p.xl[z],
                    p.wh + (size_t)z * E_ * E_, p.wl + (size_t)z * E_ * E_,
                    p.bias + z * E_,
                    nullptr, p.yh[z], p.yl[z], E_, E_, smem);
}

__global__ __launch_bounds__(256) void gemm_out(
    const __nv_bfloat16* __restrict__ Xh, const __nv_bfloat16* __restrict__ Xl,
    const __nv_bfloat16* __restrict__ Wh, const __nv_bfloat16* __restrict__ Wl,
    const float* __restrict__ bias, float* __restrict__ Yf)
{
    extern __shared__ char smem[];
    gemm_body<false>(Xh, Xl, Wh, Wl, bias, Yf, nullptr, nullptr, E_, E_, smem);
}

// ===========================================================================
// Flash attention: 128 threads / 64 q-rows per CTA (2 CTAs co-resident/SM),
// cp.async double-buffered K/V (Bc=64), warp-local softmax, split-3 MMA.
// ===========================================================================
#define FA_SMEM (2 * 32768)

__global__ __launch_bounds__(128, 2) void flash_pk(
    const __nv_bfloat16* __restrict__ Qh, const __nv_bfloat16* __restrict__ Ql,
    const __nv_bfloat16* __restrict__ Kh, const __nv_bfloat16* __restrict__ Kl,
    const __nv_bfloat16* __restrict__ Vh, const __nv_bfloat16* __restrict__ Vl,
    __nv_bfloat16* __restrict__ Oh, __nv_bfloat16* __restrict__ Ol)
{
    extern __shared__ char smem[];
    const uint32_t sb = smem_u32(smem);

    const int t    = threadIdx.x;
    const int wid  = t >> 5;       // 0..3
    const int lane = t & 31;
    const int q0   = blockIdx.x * 64;
    const int h    = blockIdx.y;
    const int b    = blockIdx.z;
    const float scale = 0.125f;

    const size_t base = (size_t)b * S_ * E_ + (size_t)h * D_;

    // ---- Q fragments straight from gmem ----
    const int qrow = q0 + wid * 16 + (lane >> 2);
    const int qcol = (lane & 3) * 2;
    uint32_t qh[4][4], ql[4][4];
#pragma unroll
    for (int ks = 0; ks < 4; ++ks) {
        const size_t o00 = base + (size_t)qrow * E_ + ks * 16 + qcol;
        qh[ks][0] = *(const uint32_t*)&Qh[o00];
        qh[ks][1] = *(const uint32_t*)&Qh[o00 + 8 * E_];
        qh[ks][2] = *(const uint32_t*)&Qh[o00 + 8];
        qh[ks][3] = *(const uint32_t*)&Qh[o00 + 8 * E_ + 8];
        ql[ks][0] = *(const uint32_t*)&Ql[o00];
        ql[ks][1] = *(const uint32_t*)&Ql[o00 + 8 * E_];
        ql[ks][2] = *(const uint32_t*)&Ql[o00 + 8];
        ql[ks][3] = *(const uint32_t*)&Ql[o00 + 8 * E_ + 8];
    }

    const int b_row = ((lane >> 4) & 1) * 8 + (lane & 7);
    const int b_kb  = ((lane >> 3) & 1) * 16;
    const int v_row = ((lane >> 3) & 1) * 8 + (lane & 7);
    const int v_db  = ((lane >> 4) & 1) * 16;

    float m0 = -INFINITY, m1 = -INFINITY, l0 = 0.0f, l1 = 0.0f;
    float oa[8][4];
#pragma unroll
    for (int nt = 0; nt < 8; ++nt)
#pragma unroll
        for (int r = 0; r < 4; ++r) oa[nt][r] = 0.0f;

    // stage loader: 4 arrays x 512 chunks of 16B, 128 threads -> 16/thread
    auto load_stage = [&](int kt, int s) {
        const uint32_t st = sb + s * 32768;
#pragma unroll
        for (int i = 0; i < 4; ++i) {
            const int f   = t + 128 * i;      // 0..511
            const int row = f >> 3;
            const int ch  = (f & 7) * 8;
            const uint32_t off = SWZ128((uint32_t)(row * 128 + ch * 2));
            const size_t go = base + (size_t)(kt + row) * E_ + ch;
            cp_async16(st + off,         &Kh[go]);
            cp_async16(st + 8192 + off,  &Kl[go]);
            cp_async16(st + 16384 + off, &Vh[go]);
            cp_async16(st + 24576 + off, &Vl[go]);
        }
        CP_COMMIT();
    };

    const int niter = S_ / 64;   // 32
    load_stage(0, 0);
    for (int it = 0; it < niter; ++it) {
        if (it + 1 < niter) { load_stage((it + 1) * 64, (it + 1) & 1); CP_WAIT(1); }
        else                { CP_WAIT(0); }
        __syncthreads();

        const uint32_t st  = sb + (it & 1) * 32768;
        const uint32_t sKh = st, sKl = st + 8192, sVh = st + 16384, sVl = st + 24576;

        // ---- S = Q K^T (split-3) ----
        float s[8][4];
#pragma unroll
        for (int nt = 0; nt < 8; ++nt)
#pragma unroll
            for (int r = 0; r < 4; ++r) s[nt][r] = 0.0f;

#pragma unroll
        for (int ks = 0; ks < 4; ++ks) {
            uint32_t bh[8][2], bl[8][2];
#pragma unroll
            for (int np = 0; np < 4; ++np) {
                const uint32_t boff =
                    SWZ128((uint32_t)((np * 16 + b_row) * 128 + ks * 32 + b_kb));
                uint32_t r4[4];
                ldsm_x4(sKh + boff, r4);
                bh[2 * np][0] = r4[0]; bh[2 * np][1] = r4[1];
                bh[2 * np + 1][0] = r4[2]; bh[2 * np + 1][1] = r4[3];
                ldsm_x4(sKl + boff, r4);
                bl[2 * np][0] = r4[0]; bl[2 * np][1] = r4[1];
                bl[2 * np + 1][0] = r4[2]; bl[2 * np + 1][1] = r4[3];
            }
#pragma unroll
            for (int nt = 0; nt < 8; ++nt) {
                mma16816(s[nt], qh[ks], bh[nt]);
                mma16816(s[nt], qh[ks], bl[nt]);
                mma16816(s[nt], ql[ks], bh[nt]);
            }
        }

        // ---- online softmax (warp-local) ----
#pragma unroll
        for (int nt = 0; nt < 8; ++nt)
#pragma unroll
            for (int r = 0; r < 4; ++r) s[nt][r] *= scale;

        float mx0 = -INFINITY, mx1 = -INFINITY;
#pragma unroll
        for (int nt = 0; nt < 8; ++nt) {
            mx0 = fmaxf(mx0, fmaxf(s[nt][0], s[nt][1]));
            mx1 = fmaxf(mx1, fmaxf(s[nt][2], s[nt][3]));
        }
        mx0 = fmaxf(mx0, __shfl_xor_sync(0xffffffffu, mx0, 1));
        mx0 = fmaxf(mx0, __shfl_xor_sync(0xffffffffu, mx0, 2));
        mx1 = fmaxf(mx1, __shfl_xor_sync(0xffffffffu, mx1, 1));
        mx1 = fmaxf(mx1, __shfl_xor_sync(0xffffffffu, mx1, 2));

        const float mn0 = fmaxf(m0, mx0);
        const float mn1 = fmaxf(m1, mx1);
        const float al0 = __expf(m0 - mn0);
        const float al1 = __expf(m1 - mn1);

        float rs0 = 0.0f, rs1 = 0.0f;
#pragma unroll
        for (int nt = 0; nt < 8; ++nt) {
            float p0 = __expf(s[nt][0] - mn0);
            float p1 = __expf(s[nt][1] - mn0);
            float p2 = __expf(s[nt][2] - mn1);
            float p3 = __expf(s[nt][3] - mn1);
            s[nt][0] = p0; s[nt][1] = p1; s[nt][2] = p2; s[nt][3] = p3;
            rs0 += p0 + p1;
            rs1 += p2 + p3;
        }
        rs0 += __shfl_xor_sync(0xffffffffu, rs0, 1);
        rs0 += __shfl_xor_sync(0xffffffffu, rs0, 2);
        rs1 += __shfl_xor_sync(0xffffffffu, rs1, 1);
        rs1 += __shfl_xor_sync(0xffffffffu, rs1, 2);

        l0 = l0 * al0 + rs0;  m0 = mn0;
        l1 = l1 * al1 + rs1;  m1 = mn1;
#pragma unroll
        for (int nt = 0; nt < 8; ++nt) {
            oa[nt][0] *= al0; oa[nt][1] *= al0;
            oa[nt][2] *= al1; oa[nt][3] *= al1;
        }

        // ---- O += P V (split-3) ----
#pragma unroll
        for (int ks = 0; ks < 4; ++ks) {
            uint32_t pah[4], pal[4];
            split2(s[2 * ks][0],     s[2 * ks][1],     pah[0], pal[0]);
            split2(s[2 * ks][2],     s[2 * ks][3],     pah[1], pal[1]);
            split2(s[2 * ks + 1][0], s[2 * ks + 1][1], pah[2], pal[2]);
            split2(s[2 * ks + 1][2], s[2 * ks + 1][3], pah[3], pal[3]);

            uint32_t vh[8][2], vl[8][2];
#pragma unroll
            for (int dp = 0; dp < 4; ++dp) {
                const uint32_t voff =
                    SWZ128((uint32_t)((ks * 16 + v_row) * 128 + dp * 32 + v_db));
                uint32_t r4[4];
                ldsm_x4_t(sVh + voff, r4);
                vh[2 * dp][0] = r4[0]; vh[2 * dp][1] = r4[1];
                vh[2 * dp + 1][0] = r4[2]; vh[2 * dp + 1][1] = r4[3];
                ldsm_x4_t(sVl + voff, r4);
                vl[2 * dp][0] = r4[0]; vl[2 * dp][1] = r4[1];
                vl[2 * dp + 1][0] = r4[2]; vl[2 * dp + 1][1] = r4[3];
            }
#pragma unroll
            for (int nt = 0; nt < 8; ++nt) {
                mma16816(oa[nt], pah, vh[nt]);
                mma16816(oa[nt], pah, vl[nt]);
                mma16816(oa[nt], pal, vh[nt]);
            }
        }
        __syncthreads();
    }

    // ---- epilogue: normalized output as split bf16 ----
    const float inv0 = 1.0f / l0;
    const float inv1 = 1.0f / l1;
    const int r0g = q0 + wid * 16 + (lane >> 2);
#pragma unroll
    for (int nt = 0; nt < 8; ++nt) {
        const int col = nt * 8 + 2 * (lane & 3);
        uint32_t h0, lo0, h1, lo1;
        split2(oa[nt][0] * inv0, oa[nt][1] * inv0, h0, lo0);
        split2(oa[nt][2] * inv1, oa[nt][3] * inv1, h1, lo1);
        const size_t o0 = base + (size_t)r0g * E_ + col;
        *(uint32_t*)&Oh[o0]           = h0;
        *(uint32_t*)&Ol[o0]           = lo0;
        *(uint32_t*)&Oh[o0 + 8 * E_]  = h1;
        *(uint32_t*)&Ol[o0 + 8 * E_]  = lo1;
    }
}

// ---------------------------------------------------------------------------
// Launch
// ---------------------------------------------------------------------------
extern "C" void kernel_launch(void* const* d_in, const int* in_sizes, int n_in,
                              void* d_out, int out_size)
{
    (void)in_sizes; (void)n_in; (void)out_size;

    const float* q     = (const float*)d_in[0];
    const float* k     = (const float*)d_in[1];
    const float* v     = (const float*)d_in[2];
    const float* w_in  = (const float*)d_in[3];
    const float* b_in  = (const float*)d_in[4];
    const float* w_out = (const float*)d_in[5];
    const float* b_out = (const float*)d_in[6];
    float* out = (float*)d_out;

    __nv_bfloat16 *inq_h, *inq_l, *ink_h, *ink_l, *inv_h, *inv_l;
    __nv_bfloat16 *win_h, *win_l, *wout_h, *wout_l;
    __nv_bfloat16 *pq_h, *pq_l, *pk_h, *pk_l, *pv_h, *pv_l, *at_h, *at_l;
    cudaGetSymbolAddress((void**)&inq_h, g_inq_h);  cudaGetSymbolAddress((void**)&inq_l, g_inq_l);
    cudaGetSymbolAddress((void**)&ink_h, g_ink_h);  cudaGetSymbolAddress((void**)&ink_l, g_ink_l);
    cudaGetSymbolAddress((void**)&inv_h, g_inv_h);  cudaGetSymbolAddress((void**)&inv_l, g_inv_l);
    cudaGetSymbolAddress((void**)&win_h, g_win_h);  cudaGetSymbolAddress((void**)&win_l, g_win_l);
    cudaGetSymbolAddress((void**)&wout_h, g_wout_h); cudaGetSymbolAddress((void**)&wout_l, g_wout_l);
    cudaGetSymbolAddress((void**)&pq_h, g_pq_h);    cudaGetSymbolAddress((void**)&pq_l, g_pq_l);
    cudaGetSymbolAddress((void**)&pk_h, g_pk_h);    cudaGetSymbolAddress((void**)&pk_l, g_pk_l);
    cudaGetSymbolAddress((void**)&pv_h, g_pv_h);    cudaGetSymbolAddress((void**)&pv_l, g_pv_l);
    cudaGetSymbolAddress((void**)&at_h, g_at_h);    cudaGetSymbolAddress((void**)&at_l, g_at_l);

    cudaFuncSetAttribute(gemm_qkv,
                         cudaFuncAttributeMaxDynamicSharedMemorySize, GEMM_SMEM);
    cudaFuncSetAttribute(gemm_out,
                         cudaFuncAttributeMaxDynamicSharedMemorySize, GEMM_SMEM);
    cudaFuncSetAttribute(flash_pk,
                         cudaFuncAttributeMaxDynamicSharedMemorySize, FA_SMEM);

    // ---- prepack (single launch, 5 segments) ----
    const int n4_io = MTOT * E_ / 4;       // 1048576
    const int n4_wi = 3 * E_ * E_ / 4;     // 786432
    const int n4_wo = E_ * E_ / 4;         // 262144
    SplitJobs sj;
    sj.src[0] = q;     sj.hi[0] = inq_h;  sj.lo[0] = inq_l;  sj.n4[0] = n4_io;
    sj.src[1] = k;     sj.hi[1] = ink_h;  sj.lo[1] = ink_l;  sj.n4[1] = n4_io;
    sj.src[2] = v;     sj.hi[2] = inv_h;  sj.lo[2] = inv_l;  sj.n4[2] = n4_io;
    sj.src[3] = w_in;  sj.hi[3] = win_h;  sj.lo[3] = win_l;  sj.n4[3] = n4_wi;
    sj.src[4] = w_out; sj.hi[4] = wout_h; sj.lo[4] = wout_l; sj.n4[4] = n4_wo;
    split_all<<<dim3(n4_io / 256, 5), 256>>>(sj);

    // ---- QKV projections (one launch) ----
    QkvPtrs qp;
    qp.xh[0] = inq_h; qp.xl[0] = inq_l; qp.yh[0] = pq_h; qp.yl[0] = pq_l;
    qp.xh[1] = ink_h; qp.xl[1] = ink_l; qp.yh[1] = pk_h; qp.yl[1] = pk_l;
    qp.xh[2] = inv_h; qp.xl[2] = inv_l; qp.yh[2] = pv_h; qp.yl[2] = pv_l;
    qp.wh = win_h; qp.wl = win_l; qp.bias = b_in;
    gemm_qkv<<<dim3(E_ / 128, MTOT / 128, 3), 256, GEMM_SMEM>>>(qp);

    // ---- attention ----
    flash_pk<<<dim3(S_ / 64, H_, B_), 128, FA_SMEM>>>(
        pq_h, pq_l, pk_h, pk_l, pv_h, pv_l, at_h, at_l);

    // ---- out projection ----
    gemm_out<<<dim3(E_ / 128, MTOT / 128), 256, GEMM_SMEM>>>(
        at_h, at_l, wout_h, wout_l, b_out, out);
}

// round 12
// speedup vs baseline: 3.6634x; 1.0636x over previous
#include <cuda_runtime.h>
#include <cuda_bf16.h>
#include <cstdint>
#include <math.h>

#define B_   2
#define S_   2048
#define E_   1024
#define H_   16
#define D_   64
#define MTOT (B_ * S_)   // 4096

// ---- prepacked bf16 scratch (hi/lo split), __device__ globals ----
__device__ __nv_bfloat16 g_inq_h[MTOT * E_], g_inq_l[MTOT * E_];
__device__ __nv_bfloat16 g_ink_h[MTOT * E_], g_ink_l[MTOT * E_];
__device__ __nv_bfloat16 g_inv_h[MTOT * E_], g_inv_l[MTOT * E_];
__device__ __nv_bfloat16 g_win_h[3 * E_ * E_], g_win_l[3 * E_ * E_];
__device__ __nv_bfloat16 g_wout_h[E_ * E_], g_wout_l[E_ * E_];
__device__ __nv_bfloat16 g_pq_h[MTOT * E_], g_pq_l[MTOT * E_];
__device__ __nv_bfloat16 g_pk_h[MTOT * E_], g_pk_l[MTOT * E_];
__device__ __nv_bfloat16 g_pv_h[MTOT * E_], g_pv_l[MTOT * E_];
__device__ __nv_bfloat16 g_at_h[MTOT * E_], g_at_l[MTOT * E_];

__device__ __forceinline__ uint32_t smem_u32(const void* p) {
    uint32_t a;
    asm("{ .reg .u64 t; cvta.to.shared.u64 t, %1; cvt.u32.u64 %0, t; }"
        : "=r"(a) : "l"(p));
    return a;
}

#define SWZ128(off) ((off) ^ (((off) >> 3) & 0x70))

__device__ __forceinline__ void cp_async16(uint32_t dst, const void* src) {
    asm volatile("cp.async.cg.shared.global [%0], [%1], 16;"
                 :: "r"(dst), "l"(src));
}
#define CP_COMMIT() asm volatile("cp.async.commit_group;" ::: "memory")
#define CP_WAIT(n)  asm volatile("cp.async.wait_group %0;" :: "n"(n) : "memory")

__device__ __forceinline__ void ldsm_x4(uint32_t addr, uint32_t* r) {
    asm volatile(
        "ldmatrix.sync.aligned.m8n8.x4.shared.b16 {%0,%1,%2,%3}, [%4];"
        : "=r"(r[0]), "=r"(r[1]), "=r"(r[2]), "=r"(r[3]) : "r"(addr));
}
__device__ __forceinline__ void ldsm_x4_t(uint32_t addr, uint32_t* r) {
    asm volatile(
        "ldmatrix.sync.aligned.m8n8.x4.trans.shared.b16 {%0,%1,%2,%3}, [%4];"
        : "=r"(r[0]), "=r"(r[1]), "=r"(r[2]), "=r"(r[3]) : "r"(addr));
}
__device__ __forceinline__ void mma16816(float* d, const uint32_t* a, const uint32_t* b) {
    asm volatile(
        "mma.sync.aligned.m16n8k16.row.col.f32.bf16.bf16.f32 "
        "{%0,%1,%2,%3}, {%4,%5,%6,%7}, {%8,%9}, {%0,%1,%2,%3};"
        : "+f"(d[0]), "+f"(d[1]), "+f"(d[2]), "+f"(d[3])
        : "r"(a[0]), "r"(a[1]), "r"(a[2]), "r"(a[3]), "r"(b[0]), "r"(b[1]));
}

__device__ __forceinline__ void split4(float4 v, uint2& h, uint2& l)
{
    __nv_bfloat162 h01 = __floats2bfloat162_rn(v.x, v.y);
    __nv_bfloat162 h23 = __floats2bfloat162_rn(v.z, v.w);
    float2 f01 = __bfloat1622float2(h01);
    float2 f23 = __bfloat1622float2(h23);
    __nv_bfloat162 l01 = __floats2bfloat162_rn(v.x - f01.x, v.y - f01.y);
    __nv_bfloat162 l23 = __floats2bfloat162_rn(v.z - f23.x, v.w - f23.y);
    h.x = *reinterpret_cast<uint32_t*>(&h01);
    h.y = *reinterpret_cast<uint32_t*>(&h23);
    l.x = *reinterpret_cast<uint32_t*>(&l01);
    l.y = *reinterpret_cast<uint32_t*>(&l23);
}
__device__ __forceinline__ void split2(float a, float b, uint32_t& hi, uint32_t& lo)
{
    __nv_bfloat162 h = __floats2bfloat162_rn(a, b);
    float2 f = __bfloat1622float2(h);
    __nv_bfloat162 l = __floats2bfloat162_rn(a - f.x, b - f.y);
    hi = *reinterpret_cast<uint32_t*>(&h);
    lo = *reinterpret_cast<uint32_t*>(&l);
}

// ===========================================================================
// Prepack: all 5 splits in one launch (grid.y = segment)
// ===========================================================================
struct SplitJobs {
    const float* src[5];
    __nv_bfloat16* hi[5];
    __nv_bfloat16* lo[5];
    int n4[5];
};

__global__ __launch_bounds__(256) void split_all(SplitJobs j)
{
    const int seg = blockIdx.y;
    const int i = blockIdx.x * 256 + threadIdx.x;
    if (i < j.n4[seg]) {
        float4 v = ((const float4*)j.src[seg])[i];
        uint2 h, l;
        split4(v, h, l);
        ((uint2*)j.hi[seg])[i] = h;
        ((uint2*)j.lo[seg])[i] = l;
    }
}

// ===========================================================================
// GEMM core (NT): tile M=64 x N=128, BK=64, 128 threads (4 warps x 64mx32n).
// Prepacked bf16, cp.async 2-stage. Stage = Ah8K Al8K Bh16K Bl16K = 48KB.
// 2 stages = 96KB -> 2 CTAs/SM. Called from persistent-tile kernels.
// ===========================================================================
#define GEMM_STAGE 49152
#define GEMM_SMEM  (2 * GEMM_STAGE)   // 98304

template<bool BF16OUT>
__device__ __forceinline__ void gemm_tile(
    const __nv_bfloat16* __restrict__ Xh, const __nv_bfloat16* __restrict__ Xl,
    const __nv_bfloat16* __restrict__ Wh, const __nv_bfloat16* __restrict__ Wl,
    const float* __restrict__ bias,
    float* __restrict__ Yf, __nv_bfloat16* __restrict__ Yh,
    __nv_bfloat16* __restrict__ Yl, int K, int N, int bm, int bn,
    uint32_t sb)
{
    const int t    = threadIdx.x;
    const int wid  = t >> 5;        // 0..3
    const int lane = t & 31;
    const int wn   = wid * 32;

    float acc[4][4][4];
#pragma unroll
    for (int i = 0; i < 4; i++)
#pragma unroll
        for (int j = 0; j < 4; j++)
#pragma unroll
            for (int r = 0; r < 4; r++) acc[i][j][r] = 0.0f;

    const int a_row = (lane & 15);
    const int a_kb  = ((lane >> 4) & 1) * 16;
    const int b_row = ((lane >> 4) & 1) * 8 + (lane & 7);
    const int b_kb  = ((lane >> 3) & 1) * 16;

    const int nchunks = K / 64;

    auto load_stage = [&](int c, int s) {
        const int k0 = c * 64;
        const uint32_t st = sb + s * GEMM_STAGE;
        // A: 64 rows x 8 chunks, hi+lo
#pragma unroll
        for (int i = 0; i < 4; ++i) {
            const int f   = t + 128 * i;      // 0..511
            const int row = f >> 3;
            const int ch  = (f & 7) * 8;
            const uint32_t off = SWZ128((uint32_t)(row * 128 + ch * 2));
            const size_t xo = (size_t)(bm + row) * K + k0 + ch;
            cp_async16(st + off,        &Xh[xo]);
            cp_async16(st + 8192 + off, &Xl[xo]);
        }
        // B: 128 rows x 8 chunks, hi+lo
#pragma unroll
        for (int i = 0; i < 8; ++i) {
            const int f   = t + 128 * i;      // 0..1023
            const int row = f >> 3;
            const int ch  = (f & 7) * 8;
            const uint32_t off = SWZ128((uint32_t)(row * 128 + ch * 2));
            const size_t wo = (size_t)(bn + row) * K + k0 + ch;
            cp_async16(st + 16384 + off, &Wh[wo]);
            cp_async16(st + 32768 + off, &Wl[wo]);
        }
        CP_COMMIT();
    };

    load_stage(0, 0);
    for (int c = 0; c < nchunks; ++c) {
        if (c + 1 < nchunks) { load_stage(c + 1, (c + 1) & 1); CP_WAIT(1); }
        else                 { CP_WAIT(0); }
        __syncthreads();

        const uint32_t st  = sb + (c & 1) * GEMM_STAGE;
        const uint32_t sAh = st, sAl = st + 8192, sBh = st + 16384, sBl = st + 32768;
#pragma unroll
        for (int ks = 0; ks < 4; ++ks) {
            const int kb = ks * 32;
            uint32_t bh[4][2], bl[4][2];
#pragma unroll
            for (int np = 0; np < 2; ++np) {
                const uint32_t boff =
                    SWZ128((uint32_t)((wn + np * 16 + b_row) * 128 + kb + b_kb));
                uint32_t r4[4];
                ldsm_x4(sBh + boff, r4);
                bh[2 * np][0] = r4[0]; bh[2 * np][1] = r4[1];
                bh[2 * np + 1][0] = r4[2]; bh[2 * np + 1][1] = r4[3];
                ldsm_x4(sBl + boff, r4);
                bl[2 * np][0] = r4[0]; bl[2 * np][1] = r4[1];
                bl[2 * np + 1][0] = r4[2]; bl[2 * np + 1][1] = r4[3];
            }
#pragma unroll
            for (int mt = 0; mt < 4; ++mt) {
                const uint32_t aoff =
                    SWZ128((uint32_t)((mt * 16 + a_row) * 128 + kb + a_kb));
                uint32_t ah[4], al[4];
                ldsm_x4(sAh + aoff, ah);
                ldsm_x4(sAl + aoff, al);
#pragma unroll
                for (int nt = 0; nt < 4; ++nt) {
                    mma16816(acc[mt][nt], ah, bh[nt]);
                    mma16816(acc[mt][nt], ah, bl[nt]);
                    mma16816(acc[mt][nt], al, bh[nt]);
                }
            }
        }
        __syncthreads();
    }

    const int cr = lane >> 2;
    const int cc = (lane & 3) * 2;
#pragma unroll
    for (int mt = 0; mt < 4; ++mt) {
        const int row0 = bm + mt * 16 + cr;
#pragma unroll
        for (int nt = 0; nt < 4; ++nt) {
            const int col = bn + wn + nt * 8 + cc;
            const float2 bv = *(const float2*)&bias[col];
            float a0 = acc[mt][nt][0] + bv.x, a1 = acc[mt][nt][1] + bv.y;
            float a2 = acc[mt][nt][2] + bv.x, a3 = acc[mt][nt][3] + bv.y;
            if (BF16OUT) {
                uint32_t h0, l0, h1, l1;
                split2(a0, a1, h0, l0);
                split2(a2, a3, h1, l1);
                *(uint32_t*)&Yh[(size_t)row0 * N + col]       = h0;
                *(uint32_t*)&Yl[(size_t)row0 * N + col]       = l0;
                *(uint32_t*)&Yh[(size_t)(row0 + 8) * N + col] = h1;
                *(uint32_t*)&Yl[(size_t)(row0 + 8) * N + col] = l1;
            } else {
                float2 v0 = {a0, a1}, v1 = {a2, a3};
                *(float2*)&Yf[(size_t)row0 * N + col]       = v0;
                *(float2*)&Yf[(size_t)(row0 + 8) * N + col] = v1;
            }
        }
    }
}

// Merged persistent QKV projection: tiles = 3 * (MTOT/64) * (E/128)
#define MT64  (MTOT / 64)        // 64
#define NT128 (E_ / 128)         // 8
#define QKV_TILES (3 * MT64 * NT128)   // 1536
#define OUT_TILES (MT64 * NT128)       // 512

struct QkvPtrs {
    const __nv_bfloat16* xh[3];
    const __nv_bfloat16* xl[3];
    __nv_bfloat16* yh[3];
    __nv_bfloat16* yl[3];
    const __nv_bfloat16* wh;
    const __nv_bfloat16* wl;
    const float* bias;
};

__global__ __launch_bounds__(128, 2) void gemm_qkv(QkvPtrs p)
{
    extern __shared__ char smem[];
    const uint32_t sb = smem_u32(smem);
    for (int tile = blockIdx.x; tile < QKV_TILES; tile += gridDim.x) {
        const int z  = tile / (MT64 * NT128);
        const int r  = tile % (MT64 * NT128);
        const int bm = (r / NT128) * 64;
        const int bn = (r % NT128) * 128;
        gemm_tile<true>(p.xh[z], p.xl[z],
                        p.wh + (size_t)z * E_ * E_, p.wl + (size_t)z * E_ * E_,
                        p.bias + z * E_,
                        nullptr, p.yh[z], p.yl[z], E_, E_, bm, bn, sb);
        __syncthreads();
    }
}

__global__ __launch_bounds__(128, 2) void gemm_out(
    const __nv_bfloat16* __restrict__ Xh, const __nv_bfloat16* __restrict__ Xl,
    const __nv_bfloat16* __restrict__ Wh, const __nv_bfloat16* __restrict__ Wl,
    const float* __restrict__ bias, float* __restrict__ Yf)
{
    extern __shared__ char smem[];
    const uint32_t sb = smem_u32(smem);
    for (int tile = blockIdx.x; tile < OUT_TILES; tile += gridDim.x) {
        const int bm = (tile / NT128) * 64;
        const int bn = (tile % NT128) * 128;
        gemm_tile<false>(Xh, Xl, Wh, Wl, bias, Yf, nullptr, nullptr,
                         E_, E_, bm, bn, sb);
        __syncthreads();
    }
}

// ===========================================================================
// Flash attention (unchanged from R10 WIN): 128 thr / 64 q-rows, 2 CTAs/SM,
// cp.async double-buffered K/V (Bc=64), warp-local softmax, split-3 MMA.
// ===========================================================================
#define FA_SMEM (2 * 32768)

__global__ __launch_bounds__(128, 2) void flash_pk(
    const __nv_bfloat16* __restrict__ Qh, const __nv_bfloat16* __restrict__ Ql,
    const __nv_bfloat16* __restrict__ Kh, const __nv_bfloat16* __restrict__ Kl,
    const __nv_bfloat16* __restrict__ Vh, const __nv_bfloat16* __restrict__ Vl,
    __nv_bfloat16* __restrict__ Oh, __nv_bfloat16* __restrict__ Ol)
{
    extern __shared__ char smem[];
    const uint32_t sb = smem_u32(smem);

    const int t    = threadIdx.x;
    const int wid  = t >> 5;
    const int lane = t & 31;
    const int q0   = blockIdx.x * 64;
    const int h    = blockIdx.y;
    const int b    = blockIdx.z;
    const float scale = 0.125f;

    const size_t base = (size_t)b * S_ * E_ + (size_t)h * D_;

    const int qrow = q0 + wid * 16 + (lane >> 2);
    const int qcol = (lane & 3) * 2;
    uint32_t qh[4][4], ql[4][4];
#pragma unroll
    for (int ks = 0; ks < 4; ++ks) {
        const size_t o00 = base + (size_t)qrow * E_ + ks * 16 + qcol;
        qh[ks][0] = *(const uint32_t*)&Qh[o00];
        qh[ks][1] = *(const uint32_t*)&Qh[o00 + 8 * E_];
        qh[ks][2] = *(const uint32_t*)&Qh[o00 + 8];
        qh[ks][3] = *(const uint32_t*)&Qh[o00 + 8 * E_ + 8];
        ql[ks][0] = *(const uint32_t*)&Ql[o00];
        ql[ks][1] = *(const uint32_t*)&Ql[o00 + 8 * E_];
        ql[ks][2] = *(const uint32_t*)&Ql[o00 + 8];
        ql[ks][3] = *(const uint32_t*)&Ql[o00 + 8 * E_ + 8];
    }

    const int b_row = ((lane >> 4) & 1) * 8 + (lane & 7);
    const int b_kb  = ((lane >> 3) & 1) * 16;
    const int v_row = ((lane >> 3) & 1) * 8 + (lane & 7);
    const int v_db  = ((lane >> 4) & 1) * 16;

    float m0 = -INFINITY, m1 = -INFINITY, l0 = 0.0f, l1 = 0.0f;
    float oa[8][4];
#pragma unroll
    for (int nt = 0; nt < 8; ++nt)
#pragma unroll
        for (int r = 0; r < 4; ++r) oa[nt][r] = 0.0f;

    auto load_stage = [&](int kt, int s) {
        const uint32_t st = sb + s * 32768;
#pragma unroll
        for (int i = 0; i < 4; ++i) {
            const int f   = t + 128 * i;
            const int row = f >> 3;
            const int ch  = (f & 7) * 8;
            const uint32_t off = SWZ128((uint32_t)(row * 128 + ch * 2));
            const size_t go = base + (size_t)(kt + row) * E_ + ch;
            cp_async16(st + off,         &Kh[go]);
            cp_async16(st + 8192 + off,  &Kl[go]);
            cp_async16(st + 16384 + off, &Vh[go]);
            cp_async16(st + 24576 + off, &Vl[go]);
        }
        CP_COMMIT();
    };

    const int niter = S_ / 64;
    load_stage(0, 0);
    for (int it = 0; it < niter; ++it) {
        if (it + 1 < niter) { load_stage((it + 1) * 64, (it + 1) & 1); CP_WAIT(1); }
        else                { CP_WAIT(0); }
        __syncthreads();

        const uint32_t st  = sb + (it & 1) * 32768;
        const uint32_t sKh = st, sKl = st + 8192, sVh = st + 16384, sVl = st + 24576;

        float s[8][4];
#pragma unroll
        for (int nt = 0; nt < 8; ++nt)
#pragma unroll
            for (int r = 0; r < 4; ++r) s[nt][r] = 0.0f;

#pragma unroll
        for (int ks = 0; ks < 4; ++ks) {
            uint32_t bh[8][2], bl[8][2];
#pragma unroll
            for (int np = 0; np < 4; ++np) {
                const uint32_t boff =
                    SWZ128((uint32_t)((np * 16 + b_row) * 128 + ks * 32 + b_kb));
                uint32_t r4[4];
                ldsm_x4(sKh + boff, r4);
                bh[2 * np][0] = r4[0]; bh[2 * np][1] = r4[1];
                bh[2 * np + 1][0] = r4[2]; bh[2 * np + 1][1] = r4[3];
                ldsm_x4(sKl + boff, r4);
                bl[2 * np][0] = r4[0]; bl[2 * np][1] = r4[1];
                bl[2 * np + 1][0] = r4[2]; bl[2 * np + 1][1] = r4[3];
            }
#pragma unroll
            for (int nt = 0; nt < 8; ++nt) {
                mma16816(s[nt], qh[ks], bh[nt]);
                mma16816(s[nt], qh[ks], bl[nt]);
                mma16816(s[nt], ql[ks], bh[nt]);
            }
        }

#pragma unroll
        for (int nt = 0; nt < 8; ++nt)
#pragma unroll
            for (int r = 0; r < 4; ++r) s[nt][r] *= scale;

        float mx0 = -INFINITY, mx1 = -INFINITY;
#pragma unroll
        for (int nt = 0; nt < 8; ++nt) {
            mx0 = fmaxf(mx0, fmaxf(s[nt][0], s[nt][1]));
            mx1 = fmaxf(mx1, fmaxf(s[nt][2], s[nt][3]));
        }
        mx0 = fmaxf(mx0, __shfl_xor_sync(0xffffffffu, mx0, 1));
        mx0 = fmaxf(mx0, __shfl_xor_sync(0xffffffffu, mx0, 2));
        mx1 = fmaxf(mx1, __shfl_xor_sync(0xffffffffu, mx1, 1));
        mx1 = fmaxf(mx1, __shfl_xor_sync(0xffffffffu, mx1, 2));

        const float mn0 = fmaxf(m0, mx0);
        const float mn1 = fmaxf(m1, mx1);
        const float al0 = __expf(m0 - mn0);
        const float al1 = __expf(m1 - mn1);

        float rs0 = 0.0f, rs1 = 0.0f;
#pragma unroll
        for (int nt = 0; nt < 8; ++nt) {
            float p0 = __expf(s[nt][0] - mn0);
            float p1 = __expf(s[nt][1] - mn0);
            float p2 = __expf(s[nt][2] - mn1);
            float p3 = __expf(s[nt][3] - mn1);
            s[nt][0] = p0; s[nt][1] = p1; s[nt][2] = p2; s[nt][3] = p3;
            rs0 += p0 + p1;
            rs1 += p2 + p3;
        }
        rs0 += __shfl_xor_sync(0xffffffffu, rs0, 1);
        rs0 += __shfl_xor_sync(0xffffffffu, rs0, 2);
        rs1 += __shfl_xor_sync(0xffffffffu, rs1, 1);
        rs1 += __shfl_xor_sync(0xffffffffu, rs1, 2);

        l0 = l0 * al0 + rs0;  m0 = mn0;
        l1 = l1 * al1 + rs1;  m1 = mn1;
#pragma unroll
        for (int nt = 0; nt < 8; ++nt) {
            oa[nt][0] *= al0; oa[nt][1] *= al0;
            oa[nt][2] *= al1; oa[nt][3] *= al1;
        }

#pragma unroll
        for (int ks = 0; ks < 4; ++ks) {
            uint32_t pah[4], pal[4];
            split2(s[2 * ks][0],     s[2 * ks][1],     pah[0], pal[0]);
            split2(s[2 * ks][2],     s[2 * ks][3],     pah[1], pal[1]);
            split2(s[2 * ks + 1][0], s[2 * ks + 1][1], pah[2], pal[2]);
            split2(s[2 * ks + 1][2], s[2 * ks + 1][3], pah[3], pal[3]);

            uint32_t vh[8][2], vl[8][2];
#pragma unroll
            for (int dp = 0; dp < 4; ++dp) {
                const uint32_t voff =
                    SWZ128((uint32_t)((ks * 16 + v_row) * 128 + dp * 32 + v_db));
                uint32_t r4[4];
                ldsm_x4_t(sVh + voff, r4);
                vh[2 * dp][0] = r4[0]; vh[2 * dp][1] = r4[1];
                vh[2 * dp + 1][0] = r4[2]; vh[2 * dp + 1][1] = r4[3];
                ldsm_x4_t(sVl + voff, r4);
                vl[2 * dp][0] = r4[0]; vl[2 * dp][1] = r4[1];
                vl[2 * dp + 1][0] = r4[2]; vl[2 * dp + 1][1] = r4[3];
            }
#pragma unroll
            for (int nt = 0; nt < 8; ++nt) {
                mma16816(oa[nt], pah, vh[nt]);
                mma16816(oa[nt], pah, vl[nt]);
                mma16816(oa[nt], pal, vh[nt]);
            }
        }
        __syncthreads();
    }

    const float inv0 = 1.0f / l0;
    const float inv1 = 1.0f / l1;
    const int r0g = q0 + wid * 16 + (lane >> 2);
#pragma unroll
    for (int nt = 0; nt < 8; ++nt) {
        const int col = nt * 8 + 2 * (lane & 3);
        uint32_t h0, lo0, h1, lo1;
        split2(oa[nt][0] * inv0, oa[nt][1] * inv0, h0, lo0);
        split2(oa[nt][2] * inv1, oa[nt][3] * inv1, h1, lo1);
        const size_t o0 = base + (size_t)r0g * E_ + col;
        *(uint32_t*)&Oh[o0]           = h0;
        *(uint32_t*)&Ol[o0]           = lo0;
        *(uint32_t*)&Oh[o0 + 8 * E_]  = h1;
        *(uint32_t*)&Ol[o0 + 8 * E_]  = lo1;
    }
}

// ---------------------------------------------------------------------------
// Launch
// ---------------------------------------------------------------------------
extern "C" void kernel_launch(void* const* d_in, const int* in_sizes, int n_in,
                              void* d_out, int out_size)
{
    (void)in_sizes; (void)n_in; (void)out_size;

    const float* q     = (const float*)d_in[0];
    const float* k     = (const float*)d_in[1];
    const float* v     = (const float*)d_in[2];
    const float* w_in  = (const float*)d_in[3];
    const float* b_in  = (const float*)d_in[4];
    const float* w_out = (const float*)d_in[5];
    const float* b_out = (const float*)d_in[6];
    float* out = (float*)d_out;

    __nv_bfloat16 *inq_h, *inq_l, *ink_h, *ink_l, *inv_h, *inv_l;
    __nv_bfloat16 *win_h, *win_l, *wout_h, *wout_l;
    __nv_bfloat16 *pq_h, *pq_l, *pk_h, *pk_l, *pv_h, *pv_l, *at_h, *at_l;
    cudaGetSymbolAddress((void**)&inq_h, g_inq_h);  cudaGetSymbolAddress((void**)&inq_l, g_inq_l);
    cudaGetSymbolAddress((void**)&ink_h, g_ink_h);  cudaGetSymbolAddress((void**)&ink_l, g_ink_l);
    cudaGetSymbolAddress((void**)&inv_h, g_inv_h);  cudaGetSymbolAddress((void**)&inv_l, g_inv_l);
    cudaGetSymbolAddress((void**)&win_h, g_win_h);  cudaGetSymbolAddress((void**)&win_l, g_win_l);
    cudaGetSymbolAddress((void**)&wout_h, g_wout_h); cudaGetSymbolAddress((void**)&wout_l, g_wout_l);
    cudaGetSymbolAddress((void**)&pq_h, g_pq_h);    cudaGetSymbolAddress((void**)&pq_l, g_pq_l);
    cudaGetSymbolAddress((void**)&pk_h, g_pk_h);    cudaGetSymbolAddress((void**)&pk_l, g_pk_l);
    cudaGetSymbolAddress((void**)&pv_h, g_pv_h);    cudaGetSymbolAddress((void**)&pv_l, g_pv_l);
    cudaGetSymbolAddress((void**)&at_h, g_at_h);    cudaGetSymbolAddress((void**)&at_l, g_at_l);

    cudaFuncSetAttribute(gemm_qkv,
                         cudaFuncAttributeMaxDynamicSharedMemorySize, GEMM_SMEM);
    cudaFuncSetAttribute(gemm_out,
                         cudaFuncAttributeMaxDynamicSharedMemorySize, GEMM_SMEM);
    cudaFuncSetAttribute(flash_pk,
                         cudaFuncAttributeMaxDynamicSharedMemorySize, FA_SMEM);

    // ---- prepack (single launch, 5 segments) ----
    const int n4_io = MTOT * E_ / 4;
    const int n4_wi = 3 * E_ * E_ / 4;
    const int n4_wo = E_ * E_ / 4;
    SplitJobs sj;
    sj.src[0] = q;     sj.hi[0] = inq_h;  sj.lo[0] = inq_l;  sj.n4[0] = n4_io;
    sj.src[1] = k;     sj.hi[1] = ink_h;  sj.lo[1] = ink_l;  sj.n4[1] = n4_io;
    sj.src[2] = v;     sj.hi[2] = inv_h;  sj.lo[2] = inv_l;  sj.n4[2] = n4_io;
    sj.src[3] = w_in;  sj.hi[3] = win_h;  sj.lo[3] = win_l;  sj.n4[3] = n4_wi;
    sj.src[4] = w_out; sj.hi[4] = wout_h; sj.lo[4] = wout_l; sj.n4[4] = n4_wo;
    split_all<<<dim3(n4_io / 256, 5), 256>>>(sj);

    // ---- QKV projections (persistent) ----
    QkvPtrs qp;
    qp.xh[0] = inq_h; qp.xl[0] = inq_l; qp.yh[0] = pq_h; qp.yl[0] = pq_l;
    qp.xh[1] = ink_h; qp.xl[1] = ink_l; qp.yh[1] = pk_h; qp.yl[1] = pk_l;
    qp.xh[2] = inv_h; qp.xl[2] = inv_l; qp.yh[2] = pv_h; qp.yl[2] = pv_l;
    qp.wh = win_h; qp.wl = win_l; qp.bias = b_in;
    gemm_qkv<<<296, 128, GEMM_SMEM>>>(qp);

    // ---- attention ----
    flash_pk<<<dim3(S_ / 64, H_, B_), 128, FA_SMEM>>>(
        pq_h, pq_l, pk_h, pk_l, pv_h, pv_l, at_h, at_l);

    // ---- out projection (persistent) ----
    gemm_out<<<296, 128, GEMM_SMEM>>>(
        at_h, at_l, wout_h, wout_l, b_out, out);
}

// round 13
// speedup vs baseline: 3.6980x; 1.0094x over previous
#include <cuda_runtime.h>
#include <cuda_bf16.h>
#include <cstdint>
#include <math.h>

#define B_   2
#define S_   2048
#define E_   1024
#define H_   16
#define D_   64
#define MTOT (B_ * S_)   // 4096

// ---- prepacked bf16 scratch (hi/lo split), __device__ globals ----
__device__ __nv_bfloat16 g_inq_h[MTOT * E_], g_inq_l[MTOT * E_];
__device__ __nv_bfloat16 g_ink_h[MTOT * E_], g_ink_l[MTOT * E_];
__device__ __nv_bfloat16 g_inv_h[MTOT * E_], g_inv_l[MTOT * E_];
__device__ __nv_bfloat16 g_win_h[3 * E_ * E_], g_win_l[3 * E_ * E_];
__device__ __nv_bfloat16 g_wout_h[E_ * E_], g_wout_l[E_ * E_];
__device__ __nv_bfloat16 g_pq_h[MTOT * E_], g_pq_l[MTOT * E_];
__device__ __nv_bfloat16 g_pk_h[MTOT * E_], g_pk_l[MTOT * E_];
__device__ __nv_bfloat16 g_pv_h[MTOT * E_], g_pv_l[MTOT * E_];
__device__ __nv_bfloat16 g_at_h[MTOT * E_], g_at_l[MTOT * E_];

__device__ __forceinline__ uint32_t smem_u32(const void* p) {
    uint32_t a;
    asm("{ .reg .u64 t; cvta.to.shared.u64 t, %1; cvt.u32.u64 %0, t; }"
        : "=r"(a) : "l"(p));
    return a;
}

#define SWZ128(off) ((off) ^ (((off) >> 3) & 0x70))

__device__ __forceinline__ void cp_async16(uint32_t dst, const void* src) {
    asm volatile("cp.async.cg.shared.global [%0], [%1], 16;"
                 :: "r"(dst), "l"(src));
}
#define CP_COMMIT() asm volatile("cp.async.commit_group;" ::: "memory")
#define CP_WAIT(n)  asm volatile("cp.async.wait_group %0;" :: "n"(n) : "memory")

__device__ __forceinline__ void ldsm_x4(uint32_t addr, uint32_t* r) {
    asm volatile(
        "ldmatrix.sync.aligned.m8n8.x4.shared.b16 {%0,%1,%2,%3}, [%4];"
        : "=r"(r[0]), "=r"(r[1]), "=r"(r[2]), "=r"(r[3]) : "r"(addr));
}
__device__ __forceinline__ void ldsm_x4_t(uint32_t addr, uint32_t* r) {
    asm volatile(
        "ldmatrix.sync.aligned.m8n8.x4.trans.shared.b16 {%0,%1,%2,%3}, [%4];"
        : "=r"(r[0]), "=r"(r[1]), "=r"(r[2]), "=r"(r[3]) : "r"(addr));
}
__device__ __forceinline__ void mma16816(float* d, const uint32_t* a, const uint32_t* b) {
    asm volatile(
        "mma.sync.aligned.m16n8k16.row.col.f32.bf16.bf16.f32 "
        "{%0,%1,%2,%3}, {%4,%5,%6,%7}, {%8,%9}, {%0,%1,%2,%3};"
        : "+f"(d[0]), "+f"(d[1]), "+f"(d[2]), "+f"(d[3])
        : "r"(a[0]), "r"(a[1]), "r"(a[2]), "r"(a[3]), "r"(b[0]), "r"(b[1]));
}

__device__ __forceinline__ void split4(float4 v, uint2& h, uint2& l)
{
    __nv_bfloat162 h01 = __floats2bfloat162_rn(v.x, v.y);
    __nv_bfloat162 h23 = __floats2bfloat162_rn(v.z, v.w);
    float2 f01 = __bfloat1622float2(h01);
    float2 f23 = __bfloat1622float2(h23);
    __nv_bfloat162 l01 = __floats2bfloat162_rn(v.x - f01.x, v.y - f01.y);
    __nv_bfloat162 l23 = __floats2bfloat162_rn(v.z - f23.x, v.w - f23.y);
    h.x = *reinterpret_cast<uint32_t*>(&h01);
    h.y = *reinterpret_cast<uint32_t*>(&h23);
    l.x = *reinterpret_cast<uint32_t*>(&l01);
    l.y = *reinterpret_cast<uint32_t*>(&l23);
}
__device__ __forceinline__ void split2(float a, float b, uint32_t& hi, uint32_t& lo)
{
    __nv_bfloat162 h = __floats2bfloat162_rn(a, b);
    float2 f = __bfloat1622float2(h);
    __nv_bfloat162 l = __floats2bfloat162_rn(a - f.x, b - f.y);
    hi = *reinterpret_cast<uint32_t*>(&h);
    lo = *reinterpret_cast<uint32_t*>(&l);
}

// ===========================================================================
// Prepack: all 5 splits in one launch (grid.y = segment)
// ===========================================================================
struct SplitJobs {
    const float* src[5];
    __nv_bfloat16* hi[5];
    __nv_bfloat16* lo[5];
    int n4[5];
};

__global__ __launch_bounds__(256) void split_all(SplitJobs j)
{
    const int seg = blockIdx.y;
    const int i = blockIdx.x * 256 + threadIdx.x;
    if (i < j.n4[seg]) {
        float4 v = ((const float4*)j.src[seg])[i];
        uint2 h, l;
        split4(v, h, l);
        ((uint2*)j.hi[seg])[i] = h;
        ((uint2*)j.lo[seg])[i] = l;
    }
}

// ===========================================================================
// GEMM core (NT): tile M=64 x N=128, BK=64, 256 threads.
// 8 warps: wm=(wid&1)*32, wn=(wid>>1)*32 -> each warp 32m x 32n (acc=32regs).
// Stage = Ah8K Al8K Bh16K Bl16K = 48KB; 2 stages = 96KB -> 2 CTAs/SM,
// 16 warps/SM (4 per SMSP). Persistent-tile kernels.
// ===========================================================================
#define GEMM_STAGE 49152
#define GEMM_SMEM  (2 * GEMM_STAGE)   // 98304

template<bool BF16OUT>
__device__ __forceinline__ void gemm_tile(
    const __nv_bfloat16* __restrict__ Xh, const __nv_bfloat16* __restrict__ Xl,
    const __nv_bfloat16* __restrict__ Wh, const __nv_bfloat16* __restrict__ Wl,
    const float* __restrict__ bias,
    float* __restrict__ Yf, __nv_bfloat16* __restrict__ Yh,
    __nv_bfloat16* __restrict__ Yl, int K, int N, int bm, int bn,
    uint32_t sb)
{
    const int t    = threadIdx.x;
    const int wid  = t >> 5;        // 0..7
    const int lane = t & 31;
    const int wm   = (wid & 1) * 32;
    const int wn   = (wid >> 1) * 32;

    float acc[2][4][4];
#pragma unroll
    for (int i = 0; i < 2; i++)
#pragma unroll
        for (int j = 0; j < 4; j++)
#pragma unroll
            for (int r = 0; r < 4; r++) acc[i][j][r] = 0.0f;

    const int a_row = (lane & 15);
    const int a_kb  = ((lane >> 4) & 1) * 16;
    const int b_row = ((lane >> 4) & 1) * 8 + (lane & 7);
    const int b_kb  = ((lane >> 3) & 1) * 16;

    const int nchunks = K / 64;

    auto load_stage = [&](int c, int s) {
        const int k0 = c * 64;
        const uint32_t st = sb + s * GEMM_STAGE;
        // A: 64 rows x 8 chunks of 16B, hi+lo (512 chunks / 256 thr = 2 it)
#pragma unroll
        for (int i = 0; i < 2; ++i) {
            const int f   = t + 256 * i;
            const int row = f >> 3;
            const int ch  = (f & 7) * 8;
            const uint32_t off = SWZ128((uint32_t)(row * 128 + ch * 2));
            const size_t xo = (size_t)(bm + row) * K + k0 + ch;
            cp_async16(st + off,        &Xh[xo]);
            cp_async16(st + 8192 + off, &Xl[xo]);
        }
        // B: 128 rows x 8 chunks, hi+lo (1024 chunks / 256 thr = 4 it)
#pragma unroll
        for (int i = 0; i < 4; ++i) {
            const int f   = t + 256 * i;
            const int row = f >> 3;
            const int ch  = (f & 7) * 8;
            const uint32_t off = SWZ128((uint32_t)(row * 128 + ch * 2));
            const size_t wo = (size_t)(bn + row) * K + k0 + ch;
            cp_async16(st + 16384 + off, &Wh[wo]);
            cp_async16(st + 32768 + off, &Wl[wo]);
        }
        CP_COMMIT();
    };

    load_stage(0, 0);
    for (int c = 0; c < nchunks; ++c) {
        if (c + 1 < nchunks) { load_stage(c + 1, (c + 1) & 1); CP_WAIT(1); }
        else                 { CP_WAIT(0); }
        __syncthreads();

        const uint32_t st  = sb + (c & 1) * GEMM_STAGE;
        const uint32_t sAh = st, sAl = st + 8192, sBh = st + 16384, sBl = st + 32768;
#pragma unroll
        for (int ks = 0; ks < 4; ++ks) {
            const int kb = ks * 32;
            uint32_t bh[4][2], bl[4][2];
#pragma unroll
            for (int np = 0; np < 2; ++np) {
                const uint32_t boff =
                    SWZ128((uint32_t)((wn + np * 16 + b_row) * 128 + kb + b_kb));
                uint32_t r4[4];
                ldsm_x4(sBh + boff, r4);
                bh[2 * np][0] = r4[0]; bh[2 * np][1] = r4[1];
                bh[2 * np + 1][0] = r4[2]; bh[2 * np + 1][1] = r4[3];
                ldsm_x4(sBl + boff, r4);
                bl[2 * np][0] = r4[0]; bl[2 * np][1] = r4[1];
                bl[2 * np + 1][0] = r4[2]; bl[2 * np + 1][1] = r4[3];
            }
#pragma unroll
            for (int mt = 0; mt < 2; ++mt) {
                const uint32_t aoff =
                    SWZ128((uint32_t)((wm + mt * 16 + a_row) * 128 + kb + a_kb));
                uint32_t ah[4], al[4];
                ldsm_x4(sAh + aoff, ah);
                ldsm_x4(sAl + aoff, al);
                // three independent passes (same per-acc order: hh, hl, lh)
#pragma unroll
                for (int nt = 0; nt < 4; ++nt) mma16816(acc[mt][nt], ah, bh[nt]);
#pragma unroll
                for (int nt = 0; nt < 4; ++nt) mma16816(acc[mt][nt], ah, bl[nt]);
#pragma unroll
                for (int nt = 0; nt < 4; ++nt) mma16816(acc[mt][nt], al, bh[nt]);
            }
        }
        __syncthreads();
    }

    const int cr = lane >> 2;
    const int cc = (lane & 3) * 2;
#pragma unroll
    for (int mt = 0; mt < 2; ++mt) {
        const int row0 = bm + wm + mt * 16 + cr;
#pragma unroll
        for (int nt = 0; nt < 4; ++nt) {
            const int col = bn + wn + nt * 8 + cc;
            const float2 bv = *(const float2*)&bias[col];
            float a0 = acc[mt][nt][0] + bv.x, a1 = acc[mt][nt][1] + bv.y;
            float a2 = acc[mt][nt][2] + bv.x, a3 = acc[mt][nt][3] + bv.y;
            if (BF16OUT) {
                uint32_t h0, l0, h1, l1;
                split2(a0, a1, h0, l0);
                split2(a2, a3, h1, l1);
                *(uint32_t*)&Yh[(size_t)row0 * N + col]       = h0;
                *(uint32_t*)&Yl[(size_t)row0 * N + col]       = l0;
                *(uint32_t*)&Yh[(size_t)(row0 + 8) * N + col] = h1;
                *(uint32_t*)&Yl[(size_t)(row0 + 8) * N + col] = l1;
            } else {
                float2 v0 = {a0, a1}, v1 = {a2, a3};
                *(float2*)&Yf[(size_t)row0 * N + col]       = v0;
                *(float2*)&Yf[(size_t)(row0 + 8) * N + col] = v1;
            }
        }
    }
}

#define MT64  (MTOT / 64)        // 64
#define NT128 (E_ / 128)         // 8
#define QKV_TILES (3 * MT64 * NT128)   // 1536
#define OUT_TILES (MT64 * NT128)       // 512

struct QkvPtrs {
    const __nv_bfloat16* xh[3];
    const __nv_bfloat16* xl[3];
    __nv_bfloat16* yh[3];
    __nv_bfloat16* yl[3];
    const __nv_bfloat16* wh;
    const __nv_bfloat16* wl;
    const float* bias;
};

__global__ __launch_bounds__(256, 2) void gemm_qkv(QkvPtrs p)
{
    extern __shared__ char smem[];
    const uint32_t sb = smem_u32(smem);
    for (int tile = blockIdx.x; tile < QKV_TILES; tile += gridDim.x) {
        const int z  = tile / (MT64 * NT128);
        const int r  = tile % (MT64 * NT128);
        const int bm = (r / NT128) * 64;
        const int bn = (r % NT128) * 128;
        gemm_tile<true>(p.xh[z], p.xl[z],
                        p.wh + (size_t)z * E_ * E_, p.wl + (size_t)z * E_ * E_,
                        p.bias + z * E_,
                        nullptr, p.yh[z], p.yl[z], E_, E_, bm, bn, sb);
        __syncthreads();
    }
}

__global__ __launch_bounds__(256, 2) void gemm_out(
    const __nv_bfloat16* __restrict__ Xh, const __nv_bfloat16* __restrict__ Xl,
    const __nv_bfloat16* __restrict__ Wh, const __nv_bfloat16* __restrict__ Wl,
    const float* __restrict__ bias, float* __restrict__ Yf)
{
    extern __shared__ char smem[];
    const uint32_t sb = smem_u32(smem);
    for (int tile = blockIdx.x; tile < OUT_TILES; tile += gridDim.x) {
        const int bm = (tile / NT128) * 64;
        const int bn = (tile % NT128) * 128;
        gemm_tile<false>(Xh, Xl, Wh, Wl, bias, Yf, nullptr, nullptr,
                         E_, E_, bm, bn, sb);
        __syncthreads();
    }
}

// ===========================================================================
// Flash attention: 128 thr / 64 q-rows, NOW 3 CTAs/SM (launch_bounds(128,3)),
// cp.async double-buffered K/V (Bc=64), warp-local softmax, split-3 MMA.
// ===========================================================================
#define FA_SMEM (2 * 32768)

__global__ __launch_bounds__(128, 3) void flash_pk(
    const __nv_bfloat16* __restrict__ Qh, const __nv_bfloat16* __restrict__ Ql,
    const __nv_bfloat16* __restrict__ Kh, const __nv_bfloat16* __restrict__ Kl,
    const __nv_bfloat16* __restrict__ Vh, const __nv_bfloat16* __restrict__ Vl,
    __nv_bfloat16* __restrict__ Oh, __nv_bfloat16* __restrict__ Ol)
{
    extern __shared__ char smem[];
    const uint32_t sb = smem_u32(smem);

    const int t    = threadIdx.x;
    const int wid  = t >> 5;
    const int lane = t & 31;
    const int q0   = blockIdx.x * 64;
    const int h    = blockIdx.y;
    const int b    = blockIdx.z;
    const float scale = 0.125f;

    const size_t base = (size_t)b * S_ * E_ + (size_t)h * D_;

    const int qrow = q0 + wid * 16 + (lane >> 2);
    const int qcol = (lane & 3) * 2;
    uint32_t qh[4][4], ql[4][4];
#pragma unroll
    for (int ks = 0; ks < 4; ++ks) {
        const size_t o00 = base + (size_t)qrow * E_ + ks * 16 + qcol;
        qh[ks][0] = *(const uint32_t*)&Qh[o00];
        qh[ks][1] = *(const uint32_t*)&Qh[o00 + 8 * E_];
        qh[ks][2] = *(const uint32_t*)&Qh[o00 + 8];
        qh[ks][3] = *(const uint32_t*)&Qh[o00 + 8 * E_ + 8];
        ql[ks][0] = *(const uint32_t*)&Ql[o00];
        ql[ks][1] = *(const uint32_t*)&Ql[o00 + 8 * E_];
        ql[ks][2] = *(const uint32_t*)&Ql[o00 + 8];
        ql[ks][3] = *(const uint32_t*)&Ql[o00 + 8 * E_ + 8];
    }

    const int b_row = ((lane >> 4) & 1) * 8 + (lane & 7);
    const int b_kb  = ((lane >> 3) & 1) * 16;
    const int v_row = ((lane >> 3) & 1) * 8 + (lane & 7);
    const int v_db  = ((lane >> 4) & 1) * 16;

    float m0 = -INFINITY, m1 = -INFINITY, l0 = 0.0f, l1 = 0.0f;
    float oa[8][4];
#pragma unroll
    for (int nt = 0; nt < 8; ++nt)
#pragma unroll
        for (int r = 0; r < 4; ++r) oa[nt][r] = 0.0f;

    auto load_stage = [&](int kt, int s) {
        const uint32_t st = sb + s * 32768;
#pragma unroll
        for (int i = 0; i < 4; ++i) {
            const int f   = t + 128 * i;
            const int row = f >> 3;
            const int ch  = (f & 7) * 8;
            const uint32_t off = SWZ128((uint32_t)(row * 128 + ch * 2));
            const size_t go = base + (size_t)(kt + row) * E_ + ch;
            cp_async16(st + off,         &Kh[go]);
            cp_async16(st + 8192 + off,  &Kl[go]);
            cp_async16(st + 16384 + off, &Vh[go]);
            cp_async16(st + 24576 + off, &Vl[go]);
        }
        CP_COMMIT();
    };

    const int niter = S_ / 64;
    load_stage(0, 0);
    for (int it = 0; it < niter; ++it) {
        if (it + 1 < niter) { load_stage((it + 1) * 64, (it + 1) & 1); CP_WAIT(1); }
        else                { CP_WAIT(0); }
        __syncthreads();

        const uint32_t st  = sb + (it & 1) * 32768;
        const uint32_t sKh = st, sKl = st + 8192, sVh = st + 16384, sVl = st + 24576;

        float s[8][4];
#pragma unroll
        for (int nt = 0; nt < 8; ++nt)
#pragma unroll
            for (int r = 0; r < 4; ++r) s[nt][r] = 0.0f;

#pragma unroll
        for (int ks = 0; ks < 4; ++ks) {
            uint32_t bh[8][2], bl[8][2];
#pragma unroll
            for (int np = 0; np < 4; ++np) {
                const uint32_t boff =
                    SWZ128((uint32_t)((np * 16 + b_row) * 128 + ks * 32 + b_kb));
                uint32_t r4[4];
                ldsm_x4(sKh + boff, r4);
                bh[2 * np][0] = r4[0]; bh[2 * np][1] = r4[1];
                bh[2 * np + 1][0] = r4[2]; bh[2 * np + 1][1] = r4[3];
                ldsm_x4(sKl + boff, r4);
                bl[2 * np][0] = r4[0]; bl[2 * np][1] = r4[1];
                bl[2 * np + 1][0] = r4[2]; bl[2 * np + 1][1] = r4[3];
            }
            // three independent passes (same per-acc order: hh, hl, lh)
#pragma unroll
            for (int nt = 0; nt < 8; ++nt) mma16816(s[nt], qh[ks], bh[nt]);
#pragma unroll
            for (int nt = 0; nt < 8; ++nt) mma16816(s[nt], qh[ks], bl[nt]);
#pragma unroll
            for (int nt = 0; nt < 8; ++nt) mma16816(s[nt], ql[ks], bh[nt]);
        }

#pragma unroll
        for (int nt = 0; nt < 8; ++nt)
#pragma unroll
            for (int r = 0; r < 4; ++r) s[nt][r] *= scale;

        float mx0 = -INFINITY, mx1 = -INFINITY;
#pragma unroll
        for (int nt = 0; nt < 8; ++nt) {
            mx0 = fmaxf(mx0, fmaxf(s[nt][0], s[nt][1]));
            mx1 = fmaxf(mx1, fmaxf(s[nt][2], s[nt][3]));
        }
        mx0 = fmaxf(mx0, __shfl_xor_sync(0xffffffffu, mx0, 1));
        mx0 = fmaxf(mx0, __shfl_xor_sync(0xffffffffu, mx0, 2));
        mx1 = fmaxf(mx1, __shfl_xor_sync(0xffffffffu, mx1, 1));
        mx1 = fmaxf(mx1, __shfl_xor_sync(0xffffffffu, mx1, 2));

        const float mn0 = fmaxf(m0, mx0);
        const float mn1 = fmaxf(m1, mx1);
        const float al0 = __expf(m0 - mn0);
        const float al1 = __expf(m1 - mn1);

        float rs0 = 0.0f, rs1 = 0.0f;
#pragma unroll
        for (int nt = 0; nt < 8; ++nt) {
            float p0 = __expf(s[nt][0] - mn0);
            float p1 = __expf(s[nt][1] - mn0);
            float p2 = __expf(s[nt][2] - mn1);
            float p3 = __expf(s[nt][3] - mn1);
            s[nt][0] = p0; s[nt][1] = p1; s[nt][2] = p2; s[nt][3] = p3;
            rs0 += p0 + p1;
            rs1 += p2 + p3;
        }
        rs0 += __shfl_xor_sync(0xffffffffu, rs0, 1);
        rs0 += __shfl_xor_sync(0xffffffffu, rs0, 2);
        rs1 += __shfl_xor_sync(0xffffffffu, rs1, 1);
        rs1 += __shfl_xor_sync(0xffffffffu, rs1, 2);

        l0 = l0 * al0 + rs0;  m0 = mn0;
        l1 = l1 * al1 + rs1;  m1 = mn1;
#pragma unroll
        for (int nt = 0; nt < 8; ++nt) {
            oa[nt][0] *= al0; oa[nt][1] *= al0;
            oa[nt][2] *= al1; oa[nt][3] *= al1;
        }

#pragma unroll
        for (int ks = 0; ks < 4; ++ks) {
            uint32_t pah[4], pal[4];
            split2(s[2 * ks][0],     s[2 * ks][1],     pah[0], pal[0]);
            split2(s[2 * ks][2],     s[2 * ks][3],     pah[1], pal[1]);
            split2(s[2 * ks + 1][0], s[2 * ks + 1][1], pah[2], pal[2]);
            split2(s[2 * ks + 1][2], s[2 * ks + 1][3], pah[3], pal[3]);

            uint32_t vh[8][2], vl[8][2];
#pragma unroll
            for (int dp = 0; dp < 4; ++dp) {
                const uint32_t voff =
                    SWZ128((uint32_t)((ks * 16 + v_row) * 128 + dp * 32 + v_db));
                uint32_t r4[4];
                ldsm_x4_t(sVh + voff, r4);
                vh[2 * dp][0] = r4[0]; vh[2 * dp][1] = r4[1];
                vh[2 * dp + 1][0] = r4[2]; vh[2 * dp + 1][1] = r4[3];
                ldsm_x4_t(sVl + voff, r4);
                vl[2 * dp][0] = r4[0]; vl[2 * dp][1] = r4[1];
                vl[2 * dp + 1][0] = r4[2]; vl[2 * dp + 1][1] = r4[3];
            }
            // three independent passes (same per-acc order: hh, hl, lh)
#pragma unroll
            for (int nt = 0; nt < 8; ++nt) mma16816(oa[nt], pah, vh[nt]);
#pragma unroll
            for (int nt = 0; nt < 8; ++nt) mma16816(oa[nt], pah, vl[nt]);
#pragma unroll
            for (int nt = 0; nt < 8; ++nt) mma16816(oa[nt], pal, vh[nt]);
        }
        __syncthreads();
    }

    const float inv0 = 1.0f / l0;
    const float inv1 = 1.0f / l1;
    const int r0g = q0 + wid * 16 + (lane >> 2);
#pragma unroll
    for (int nt = 0; nt < 8; ++nt) {
        const int col = nt * 8 + 2 * (lane & 3);
        uint32_t h0, lo0, h1, lo1;
        split2(oa[nt][0] * inv0, oa[nt][1] * inv0, h0, lo0);
        split2(oa[nt][2] * inv1, oa[nt][3] * inv1, h1, lo1);
        const size_t o0 = base + (size_t)r0g * E_ + col;
        *(uint32_t*)&Oh[o0]           = h0;
        *(uint32_t*)&Ol[o0]           = lo0;
        *(uint32_t*)&Oh[o0 + 8 * E_]  = h1;
        *(uint32_t*)&Ol[o0 + 8 * E_]  = lo1;
    }
}

// ---------------------------------------------------------------------------
// Launch
// ---------------------------------------------------------------------------
extern "C" void kernel_launch(void* const* d_in, const int* in_sizes, int n_in,
                              void* d_out, int out_size)
{
    (void)in_sizes; (void)n_in; (void)out_size;

    const float* q     = (const float*)d_in[0];
    const float* k     = (const float*)d_in[1];
    const float* v     = (const float*)d_in[2];
    const float* w_in  = (const float*)d_in[3];
    const float* b_in  = (const float*)d_in[4];
    const float* w_out = (const float*)d_in[5];
    const float* b_out = (const float*)d_in[6];
    float* out = (float*)d_out;

    __nv_bfloat16 *inq_h, *inq_l, *ink_h, *ink_l, *inv_h, *inv_l;
    __nv_bfloat16 *win_h, *win_l, *wout_h, *wout_l;
    __nv_bfloat16 *pq_h, *pq_l, *pk_h, *pk_l, *pv_h, *pv_l, *at_h, *at_l;
    cudaGetSymbolAddress((void**)&inq_h, g_inq_h);  cudaGetSymbolAddress((void**)&inq_l, g_inq_l);
    cudaGetSymbolAddress((void**)&ink_h, g_ink_h);  cudaGetSymbolAddress((void**)&ink_l, g_ink_l);
    cudaGetSymbolAddress((void**)&inv_h, g_inv_h);  cudaGetSymbolAddress((void**)&inv_l, g_inv_l);
    cudaGetSymbolAddress((void**)&win_h, g_win_h);  cudaGetSymbolAddress((void**)&win_l, g_win_l);
    cudaGetSymbolAddress((void**)&wout_h, g_wout_h); cudaGetSymbolAddress((void**)&wout_l, g_wout_l);
    cudaGetSymbolAddress((void**)&pq_h, g_pq_h);    cudaGetSymbolAddress((void**)&pq_l, g_pq_l);
    cudaGetSymbolAddress((void**)&pk_h, g_pk_h);    cudaGetSymbolAddress((void**)&pk_l, g_pk_l);
    cudaGetSymbolAddress((void**)&pv_h, g_pv_h);    cudaGetSymbolAddress((void**)&pv_l, g_pv_l);
    cudaGetSymbolAddress((void**)&at_h, g_at_h);    cudaGetSymbolAddress((void**)&at_l, g_at_l);

    cudaFuncSetAttribute(gemm_qkv,
                         cudaFuncAttributeMaxDynamicSharedMemorySize, GEMM_SMEM);
    cudaFuncSetAttribute(gemm_out,
                         cudaFuncAttributeMaxDynamicSharedMemorySize, GEMM_SMEM);
    cudaFuncSetAttribute(flash_pk,
                         cudaFuncAttributeMaxDynamicSharedMemorySize, FA_SMEM);

    // ---- prepack (single launch, 5 segments) ----
    const int n4_io = MTOT * E_ / 4;
    const int n4_wi = 3 * E_ * E_ / 4;
    const int n4_wo = E_ * E_ / 4;
    SplitJobs sj;
    sj.src[0] = q;     sj.hi[0] = inq_h;  sj.lo[0] = inq_l;  sj.n4[0] = n4_io;
    sj.src[1] = k;     sj.hi[1] = ink_h;  sj.lo[1] = ink_l;  sj.n4[1] = n4_io;
    sj.src[2] = v;     sj.hi[2] = inv_h;  sj.lo[2] = inv_l;  sj.n4[2] = n4_io;
    sj.src[3] = w_in;  sj.hi[3] = win_h;  sj.lo[3] = win_l;  sj.n4[3] = n4_wi;
    sj.src[4] = w_out; sj.hi[4] = wout_h; sj.lo[4] = wout_l; sj.n4[4] = n4_wo;
    split_all<<<dim3(n4_io / 256, 5), 256>>>(sj);

    // ---- QKV projections (persistent) ----
    QkvPtrs qp;
    qp.xh[0] = inq_h; qp.xl[0] = inq_l; qp.yh[0] = pq_h; qp.yl[0] = pq_l;
    qp.xh[1] = ink_h; qp.xl[1] = ink_l; qp.yh[1] = pk_h; qp.yl[1] = pk_l;
    qp.xh[2] = inv_h; qp.xl[2] = inv_l; qp.yh[2] = pv_h; qp.yl[2] = pv_l;
    qp.wh = win_h; qp.wl = win_l; qp.bias = b_in;
    gemm_qkv<<<296, 256, GEMM_SMEM>>>(qp);

    // ---- attention ----
    flash_pk<<<dim3(S_ / 64, H_, B_), 128, FA_SMEM>>>(
        pq_h, pq_l, pk_h, pk_l, pv_h, pv_l, at_h, at_l);

    // ---- out projection (persistent) ----
    gemm_out<<<296, 256, GEMM_SMEM>>>(
        at_h, at_l, wout_h, wout_l, b_out, out);
}